// round 2
// baseline (speedup 1.0000x reference)
#include <cuda_runtime.h>

// Problem constants
#define TT 2048
#define DD 64
#define NHEAD 12
#define BB 4
#define NG (BB*NHEAD)      // 48 "heads" after flat reshape
#define MM (BB*TT)         // 8192 rows
#define HKDIM (NHEAD*DD)   // 768 cols

// Scratch (static device globals — no allocation allowed)
__device__ float g_Q[MM*HKDIM];
__device__ float g_K[MM*HKDIM];
__device__ float g_V[MM*HKDIM];
__device__ float g_Z[MM*HKDIM];

// ---------------------------------------------------------------------------
// GEMM1: QKV = x @ W{q,k,v}.  x: (8192,64), W: (64,768), out: (8192,768)
// grid (12, 128, 3), block 256.  64x64 tile, K=64 single pass.
// ---------------------------------------------------------------------------
__global__ __launch_bounds__(256) void qkv_gemm(
    const float* __restrict__ x, const float* __restrict__ Wq,
    const float* __restrict__ Wk, const float* __restrict__ Wv) {
  __shared__ float sXt[64*64];   // [k][i], stride 64
  __shared__ float sW[64*68];    // [k][j], stride 68 (16B-aligned rows)
  const int nt  = blockIdx.x;    // 0..11
  const int mt  = blockIdx.y;    // 0..127
  const int mat = blockIdx.z;    // 0,1,2 -> q,k,v
  const float* W = (mat == 0) ? Wq : ((mat == 1) ? Wk : Wv);
  float* out     = (mat == 0) ? g_Q : ((mat == 1) ? g_K : g_V);
  const int tid = threadIdx.x;
  const int m0 = mt*64, n0 = nt*64;

  // Load X tile (transpose) + W tile (natural)
  {
    const int i  = tid >> 2;
    const int k0 = (tid & 3) * 16;
    #pragma unroll
    for (int u = 0; u < 4; u++) {
      float4 v = *(const float4*)(x + (m0 + i)*64 + k0 + 4*u);
      const int k = k0 + 4*u;
      sXt[(k+0)*64 + i] = v.x;
      sXt[(k+1)*64 + i] = v.y;
      sXt[(k+2)*64 + i] = v.z;
      sXt[(k+3)*64 + i] = v.w;
    }
    const int kk = tid >> 2;
    const int j0 = (tid & 3) * 16;
    #pragma unroll
    for (int u = 0; u < 4; u++) {
      *(float4*)&sW[kk*68 + j0 + 4*u] =
          *(const float4*)(W + kk*768 + n0 + j0 + 4*u);
    }
  }
  __syncthreads();

  const int ty = tid >> 4, tx = tid & 15;
  float acc[4][4] = {};
  #pragma unroll 16
  for (int k = 0; k < 64; k++) {
    float4 a  = *(const float4*)&sXt[k*64 + 4*ty];
    float2 b0 = *(const float2*)&sW[k*68 + 2*tx];
    float2 b1 = *(const float2*)&sW[k*68 + 32 + 2*tx];
    float av[4] = {a.x, a.y, a.z, a.w};
    float bv[4] = {b0.x, b0.y, b1.x, b1.y};
    #pragma unroll
    for (int r = 0; r < 4; r++)
      #pragma unroll
      for (int c = 0; c < 4; c++)
        acc[r][c] = fmaf(av[r], bv[c], acc[r][c]);
  }

  #pragma unroll
  for (int r = 0; r < 4; r++) {
    const int m = m0 + 4*ty + r;
    float2 o0 = make_float2(acc[r][0], acc[r][1]);
    float2 o1 = make_float2(acc[r][2], acc[r][3]);
    *(float2*)(out + m*768 + n0 + 2*tx)      = o0;
    *(float2*)(out + m*768 + n0 + 32 + 2*tx) = o1;
  }
}

// ---------------------------------------------------------------------------
// Attention (flash-style, fp32).  Per reference:
//   S[i,j] = sum_d K[i,d]*Q[j,d] / 8 ; P = softmax_j(S) ; Z = P @ V
// grid (32, 48): blockIdx.x = i-tile (64 rows of K), blockIdx.y = head.
// 128 threads; thread (tr=tid/8, tc=tid%8) owns rows i0=4tr..+3 and
// cols/dims {4tc..4tc+3} U {32+4tc..+3}.
// smem: sKt [d][i] stride 64 | union(sQt [d][j] stride 64,
//       sP [j][i] stride 68 + XOR swizzle) | sV [j][d] stride 68.
// P word index: j*68 + (i ^ (4*((j>>2)&7))) -> conflict-free STS.128 phases
// (banks 20*tc mod 32 all distinct) and broadcast LDS.128 phases.
// ---------------------------------------------------------------------------
#define SMEM_ATTN ((4096 + 4352 + 4352) * 4)

__global__ __launch_bounds__(128, 4) void attn_kernel() {
  extern __shared__ float sm[];
  float* sKt = sm;                  // 64*64
  float* sQP = sm + 4096;           // max(64*64 Qt, 64*68 P) = 4352
  float* sV  = sm + 4096 + 4352;    // 64*68

  const int g  = blockIdx.y;
  const int it = blockIdx.x;
  const float* Qb = g_Q + g*(TT*DD);
  const float* Kb = g_K + g*(TT*DD);
  const float* Vb = g_V + g*(TT*DD);
  float*       Zb = g_Z + g*(TT*DD);

  const int tid = threadIdx.x;
  const int tr = tid >> 3, tc = tid & 7;
  const int i0 = 4*tr;

  // Load K tile transposed: sKt[d][i] = K[it*64+i, d]
  {
    const int i  = tid >> 1;
    const int d0 = (tid & 1) * 32;
    const float* src = Kb + (it*64 + i)*64 + d0;
    #pragma unroll
    for (int u = 0; u < 8; u++) {
      float4 v = *(const float4*)(src + 4*u);
      const int d = d0 + 4*u;
      sKt[(d+0)*64 + i] = v.x;
      sKt[(d+1)*64 + i] = v.y;
      sKt[(d+2)*64 + i] = v.z;
      sKt[(d+3)*64 + i] = v.w;
    }
  }

  float m[4], l[4], acc[4][8];
  #pragma unroll
  for (int r = 0; r < 4; r++) {
    m[r] = -1e30f; l[r] = 0.f;
    #pragma unroll
    for (int c = 0; c < 8; c++) acc[r][c] = 0.f;
  }

  for (int jt = 0; jt < 32; jt++) {
    // Load Q tile (transposed into sQP) and V tile (natural into sV)
    {
      const int j  = tid >> 1;
      const int d0 = (tid & 1) * 32;
      const float* qsrc = Qb + (jt*64 + j)*64 + d0;
      const float* vsrc = Vb + (jt*64 + j)*64 + d0;
      #pragma unroll
      for (int u = 0; u < 8; u++) {
        float4 v = *(const float4*)(qsrc + 4*u);
        const int d = d0 + 4*u;
        sQP[(d+0)*64 + j] = v.x;
        sQP[(d+1)*64 + j] = v.y;
        sQP[(d+2)*64 + j] = v.z;
        sQP[(d+3)*64 + j] = v.w;
        *(float4*)&sV[j*68 + d0 + 4*u] = *(const float4*)(vsrc + 4*u);
      }
    }
    __syncthreads();

    // S fragment: s[r][c]; c<4 -> j=4tc+c, c>=4 -> j=32+4tc+(c-4)
    float s[4][8];
    #pragma unroll
    for (int r = 0; r < 4; r++)
      #pragma unroll
      for (int c = 0; c < 8; c++) s[r][c] = 0.f;

    #pragma unroll 8
    for (int d = 0; d < 64; d++) {
      float4 a  = *(const float4*)&sKt[d*64 + i0];
      float4 b0 = *(const float4*)&sQP[d*64 + 4*tc];
      float4 b1 = *(const float4*)&sQP[d*64 + 32 + 4*tc];
      float av[4] = {a.x, a.y, a.z, a.w};
      float bv[8] = {b0.x, b0.y, b0.z, b0.w, b1.x, b1.y, b1.z, b1.w};
      #pragma unroll
      for (int r = 0; r < 4; r++)
        #pragma unroll
        for (int c = 0; c < 8; c++)
          s[r][c] = fmaf(av[r], bv[c], s[r][c]);
    }

    #pragma unroll
    for (int r = 0; r < 4; r++)
      #pragma unroll
      for (int c = 0; c < 8; c++) s[r][c] *= 0.125f;

    // Online softmax update (rows shared across the 8 tc-lanes of this tr)
    #pragma unroll
    for (int r = 0; r < 4; r++) {
      float tm = fmaxf(fmaxf(fmaxf(s[r][0], s[r][1]), fmaxf(s[r][2], s[r][3])),
                       fmaxf(fmaxf(s[r][4], s[r][5]), fmaxf(s[r][6], s[r][7])));
      tm = fmaxf(tm, __shfl_xor_sync(0xffffffffu, tm, 1));
      tm = fmaxf(tm, __shfl_xor_sync(0xffffffffu, tm, 2));
      tm = fmaxf(tm, __shfl_xor_sync(0xffffffffu, tm, 4));
      const float mn   = fmaxf(m[r], tm);
      const float corr = __expf(m[r] - mn);
      m[r] = mn;
      float rs = 0.f;
      #pragma unroll
      for (int c = 0; c < 8; c++) {
        const float p = __expf(s[r][c] - mn);
        s[r][c] = p;
        rs += p;
      }
      rs += __shfl_xor_sync(0xffffffffu, rs, 1);
      rs += __shfl_xor_sync(0xffffffffu, rs, 2);
      rs += __shfl_xor_sync(0xffffffffu, rs, 4);
      l[r] = l[r]*corr + rs;
      #pragma unroll
      for (int c = 0; c < 8; c++) acc[r][c] *= corr;
    }

    __syncthreads();   // sQP reads done -> safe to overwrite with P

    // Write P transposed (swizzled): word = j*68 + (i0 ^ 4*((j>>2)&7))
    #pragma unroll
    for (int h = 0; h < 2; h++)
      #pragma unroll
      for (int q = 0; q < 4; q++) {
        const int j = 32*h + 4*tc + q;
        const int swz = 4*((j >> 2) & 7);
        float4 pv = make_float4(s[0][4*h+q], s[1][4*h+q], s[2][4*h+q], s[3][4*h+q]);
        *(float4*)&sQP[j*68 + (i0 ^ swz)] = pv;
      }
    __syncthreads();

    // Z += P @ V (acc cols: c<4 -> d=4tc+c, c>=4 -> d=32+4tc+(c-4))
    #pragma unroll 8
    for (int j = 0; j < 64; j++) {
      const int swz = 4*((j >> 2) & 7);
      float4 p  = *(const float4*)&sQP[j*68 + (i0 ^ swz)];
      float4 v0 = *(const float4*)&sV[j*68 + 4*tc];
      float4 v1 = *(const float4*)&sV[j*68 + 32 + 4*tc];
      float pv[4] = {p.x, p.y, p.z, p.w};
      float vv[8] = {v0.x, v0.y, v0.z, v0.w, v1.x, v1.y, v1.z, v1.w};
      #pragma unroll
      for (int r = 0; r < 4; r++)
        #pragma unroll
        for (int c = 0; c < 8; c++)
          acc[r][c] = fmaf(pv[r], vv[c], acc[r][c]);
    }
    __syncthreads();   // before next tile's loads overwrite sQP/sV
  }

  // Epilogue: Z[i,d] = acc/l
  #pragma unroll
  for (int r = 0; r < 4; r++) {
    const float inv = 1.f / l[r];
    const int ig = it*64 + i0 + r;
    float4 o0 = make_float4(acc[r][0]*inv, acc[r][1]*inv, acc[r][2]*inv, acc[r][3]*inv);
    float4 o1 = make_float4(acc[r][4]*inv, acc[r][5]*inv, acc[r][6]*inv, acc[r][7]*inv);
    *(float4*)(Zb + ig*64 + 4*tc)      = o0;
    *(float4*)(Zb + ig*64 + 32 + 4*tc) = o1;
  }
}

// ---------------------------------------------------------------------------
// GEMM3: out = Z @ Wo.  Z: (8192,768), Wo: (768,64), out: (8192,64)
// grid 128, block 256.  64x64 tile, 12 K-chunks of 64.
// ---------------------------------------------------------------------------
__global__ __launch_bounds__(256) void out_gemm(const float* __restrict__ Wo,
                                                float* __restrict__ out) {
  __shared__ float sZt[64*64];   // [k][i]
  __shared__ float sW[64*68];    // [k][j], stride 68 (16B-aligned rows)
  const int mt = blockIdx.x;
  const int tid = threadIdx.x;
  const int m0 = mt*64;
  const int ty = tid >> 4, tx = tid & 15;
  float acc[4][4] = {};

  for (int kt = 0; kt < 12; kt++) {
    {
      const int i  = tid >> 2;
      const int k0 = (tid & 3) * 16;
      #pragma unroll
      for (int u = 0; u < 4; u++) {
        float4 v = *(const float4*)(g_Z + (m0 + i)*768 + kt*64 + k0 + 4*u);
        const int k = k0 + 4*u;
        sZt[(k+0)*64 + i] = v.x;
        sZt[(k+1)*64 + i] = v.y;
        sZt[(k+2)*64 + i] = v.z;
        sZt[(k+3)*64 + i] = v.w;
      }
      const int kk = tid >> 2;
      const int j0 = (tid & 3) * 16;
      #pragma unroll
      for (int u = 0; u < 4; u++) {
        *(float4*)&sW[kk*68 + j0 + 4*u] =
            *(const float4*)(Wo + (kt*64 + kk)*64 + j0 + 4*u);
      }
    }
    __syncthreads();

    #pragma unroll 16
    for (int k = 0; k < 64; k++) {
      float4 a  = *(const float4*)&sZt[k*64 + 4*ty];
      float2 b0 = *(const float2*)&sW[k*68 + 2*tx];
      float2 b1 = *(const float2*)&sW[k*68 + 32 + 2*tx];
      float av[4] = {a.x, a.y, a.z, a.w};
      float bv[4] = {b0.x, b0.y, b1.x, b1.y};
      #pragma unroll
      for (int r = 0; r < 4; r++)
        #pragma unroll
        for (int c = 0; c < 4; c++)
          acc[r][c] = fmaf(av[r], bv[c], acc[r][c]);
    }
    __syncthreads();
  }

  #pragma unroll
  for (int r = 0; r < 4; r++) {
    const int mrow = m0 + 4*ty + r;
    float2 o0 = make_float2(acc[r][0], acc[r][1]);
    float2 o1 = make_float2(acc[r][2], acc[r][3]);
    *(float2*)(out + mrow*64 + 2*tx)      = o0;
    *(float2*)(out + mrow*64 + 32 + 2*tx) = o1;
  }
}

// ---------------------------------------------------------------------------
extern "C" void kernel_launch(void* const* d_in, const int* in_sizes, int n_in,
                              void* d_out, int out_size) {
  const float* x  = (const float*)d_in[0];
  const float* Wq = (const float*)d_in[1];
  const float* Wk = (const float*)d_in[2];
  const float* Wv = (const float*)d_in[3];
  const float* Wo = (const float*)d_in[4];
  float* out = (float*)d_out;

  qkv_gemm<<<dim3(12, 128, 3), 256>>>(x, Wq, Wk, Wv);

  cudaFuncSetAttribute(attn_kernel, cudaFuncAttributeMaxDynamicSharedMemorySize,
                       SMEM_ATTN);
  attn_kernel<<<dim3(32, 48), 128, SMEM_ATTN>>>();

  out_gemm<<<128, 256>>>(Wo, out);
}

// round 4
// speedup vs baseline: 3.8393x; 3.8393x over previous
#include <cuda_runtime.h>
#include <cuda_fp16.h>
#include <cstdint>

#define TT 2048
#define DD 64
#define NG 48
#define GSZ (TT*DD)        // 131072 elements per flat "head"

// ---- scratch (device globals; no allocation allowed) ----------------------
__device__ __half g_Qh[(size_t)NG*GSZ];
__device__ __half g_Kh[(size_t)NG*GSZ];
__device__ __half g_Kl[(size_t)NG*GSZ];
__device__ __half g_Vh[(size_t)NG*GSZ];
__device__ float  g_Z [(size_t)NG*GSZ];

// ---- helpers ---------------------------------------------------------------
__device__ __forceinline__ uint32_t smem_u32(const void* p) {
  uint32_t a;
  asm("{ .reg .u64 t; cvta.to.shared.u64 t, %1; cvt.u32.u64 %0, t; }"
      : "=r"(a) : "l"(p));
  return a;
}
__device__ __forceinline__ void ldmat4(uint32_t (&r)[4], uint32_t addr) {
  asm volatile("ldmatrix.sync.aligned.m8n8.x4.shared.b16 {%0,%1,%2,%3}, [%4];"
    : "=r"(r[0]), "=r"(r[1]), "=r"(r[2]), "=r"(r[3]) : "r"(addr));
}
__device__ __forceinline__ void ldmat4t(uint32_t (&r)[4], uint32_t addr) {
  asm volatile("ldmatrix.sync.aligned.m8n8.x4.trans.shared.b16 {%0,%1,%2,%3}, [%4];"
    : "=r"(r[0]), "=r"(r[1]), "=r"(r[2]), "=r"(r[3]) : "r"(addr));
}
__device__ __forceinline__ void mma16816(float (&c)[4], const uint32_t (&a)[4],
                                         uint32_t b0, uint32_t b1) {
  asm volatile("mma.sync.aligned.m16n8k16.row.col.f32.f16.f16.f32 "
    "{%0,%1,%2,%3}, {%4,%5,%6,%7}, {%8,%9}, {%0,%1,%2,%3};"
    : "+f"(c[0]), "+f"(c[1]), "+f"(c[2]), "+f"(c[3])
    : "r"(a[0]), "r"(a[1]), "r"(a[2]), "r"(a[3]), "r"(b0), "r"(b1));
}
__device__ __forceinline__ uint32_t pack_h2(float a, float b) {
  __half2 h = __floats2half2_rn(a, b);
  return *(uint32_t*)&h;
}

// ---------------------------------------------------------------------------
// GEMM1: QKV = x @ W.  Q -> fp16; K -> fp16 hi/lo; V -> fp16.
// grid (12, 128, 3), block 256.
// ---------------------------------------------------------------------------
__global__ __launch_bounds__(256) void qkv_gemm(
    const float* __restrict__ x, const float* __restrict__ Wq,
    const float* __restrict__ Wk, const float* __restrict__ Wv) {
  __shared__ float sXt[64*64];
  __shared__ float sW[64*68];
  const int nt = blockIdx.x, mt = blockIdx.y, mat = blockIdx.z;
  const float* W = (mat == 0) ? Wq : ((mat == 1) ? Wk : Wv);
  const int tid = threadIdx.x;
  const int m0 = mt*64, n0 = nt*64;

  {
    const int i  = tid >> 2;
    const int k0 = (tid & 3) * 16;
    #pragma unroll
    for (int u = 0; u < 4; u++) {
      float4 v = *(const float4*)(x + (m0 + i)*64 + k0 + 4*u);
      const int k = k0 + 4*u;
      sXt[(k+0)*64 + i] = v.x; sXt[(k+1)*64 + i] = v.y;
      sXt[(k+2)*64 + i] = v.z; sXt[(k+3)*64 + i] = v.w;
    }
    const int kk = tid >> 2;
    const int j0 = (tid & 3) * 16;
    #pragma unroll
    for (int u = 0; u < 4; u++)
      *(float4*)&sW[kk*68 + j0 + 4*u] = *(const float4*)(W + kk*768 + n0 + j0 + 4*u);
  }
  __syncthreads();

  const int ty = tid >> 4, tx = tid & 15;
  float acc[4][4] = {};
  #pragma unroll 16
  for (int k = 0; k < 64; k++) {
    float4 a  = *(const float4*)&sXt[k*64 + 4*ty];
    float2 b0 = *(const float2*)&sW[k*68 + 2*tx];
    float2 b1 = *(const float2*)&sW[k*68 + 32 + 2*tx];
    float av[4] = {a.x, a.y, a.z, a.w};
    float bv[4] = {b0.x, b0.y, b1.x, b1.y};
    #pragma unroll
    for (int r = 0; r < 4; r++)
      #pragma unroll
      for (int c = 0; c < 4; c++) acc[r][c] = fmaf(av[r], bv[c], acc[r][c]);
  }

  #pragma unroll
  for (int r = 0; r < 4; r++) {
    const size_t e = (size_t)(m0 + 4*ty + r)*768 + n0;
    #pragma unroll
    for (int hh = 0; hh < 2; hh++) {
      const float a = acc[r][2*hh+0], b = acc[r][2*hh+1];
      const size_t idx = e + 32*hh + 2*tx;
      if (mat == 0) {
        *(uint32_t*)(g_Qh + idx) = pack_h2(a, b);
      } else if (mat == 1) {
        const float ha = __half2float(__float2half_rn(a));
        const float hb = __half2float(__float2half_rn(b));
        *(uint32_t*)(g_Kh + idx) = pack_h2(a, b);
        *(uint32_t*)(g_Kl + idx) = pack_h2(a - ha, b - hb);
      } else {
        *(uint32_t*)(g_Vh + idx) = pack_h2(a, b);
      }
    }
  }
}

// ---------------------------------------------------------------------------
// HMMA flash attention.  grid (16 i-tiles, 48 heads), 256 threads (8 warps).
// S[i,j] = K_i . Q_j / 8 (K split hi/lo fp16, Q fp16) ; no-max softmax ;
// Z = P @ V (P split hi/lo fp16, V fp16).  All smem rows 128B, XOR swizzle.
// Warp grid 4x2: warp (wr, wc) owns i rows wr*32..+31, j/d cols wc*32..+31.
// ---------------------------------------------------------------------------
#define OFF_KH 0
#define OFF_KL 16384
#define OFF_Q  32768
#define OFF_V  40960
#define OFF_PH 49152
#define OFF_PL 65536
#define OFF_L  81920
#define OFF_INV 82944
#define SMEM_ATT (82944 + 512)

__global__ __launch_bounds__(256, 2) void attn_mma() {
  extern __shared__ char smc[];
  const uint32_t sb = smem_u32(smc);
  const uint32_t sKh = sb + OFF_KH, sKl = sb + OFF_KL;
  const uint32_t sQ  = sb + OFF_Q,  sV  = sb + OFF_V;
  const uint32_t sPh = sb + OFF_PH, sPl = sb + OFF_PL;
  float* sL   = (float*)(smc + OFF_L);     // [2][128]
  float* sInv = (float*)(smc + OFF_INV);   // [128]

  const int g = blockIdx.y, it = blockIdx.x;
  const int tid = threadIdx.x;
  const int wid = tid >> 5, l = tid & 31;
  const int wr = wid & 3, wc = wid >> 2;

  const char* Qg = (const char*)(g_Qh + (size_t)g*GSZ);
  const char* Khg = (const char*)(g_Kh + (size_t)g*GSZ);
  const char* Klg = (const char*)(g_Kl + (size_t)g*GSZ);
  const char* Vg = (const char*)(g_Vh + (size_t)g*GSZ);

  // ldmatrix lane geometry (A-style also serves trans-V; B-style serves Q)
  const int arow = (l & 7) + (((l >> 3) & 1) << 3);   // 0..15
  const int achk = l >> 4;                            // 0/1
  const int brow = (l & 7) + ((l >> 4) << 3);
  const int bchk = (l >> 3) & 1;
  const int axor = l & 7, bxor = l & 7;

  // ---- load K i-tile (128x64 hi + lo), swizzled ----
  #pragma unroll
  for (int u = 0; u < 4; u++) {
    const int idx = tid + 256*u;          // 1024 16B chunks
    const int row = idx >> 3, c = idx & 7;
    const uint32_t go = (uint32_t)(it*128 + row)*128 + c*16;
    const uint32_t so = (uint32_t)row*128 + (uint32_t)((c ^ (row & 7)) << 4);
    *(uint4*)(smc + OFF_KH + so) = *(const uint4*)(Khg + go);
    *(uint4*)(smc + OFF_KL + so) = *(const uint4*)(Klg + go);
  }

  float zacc[2][4][4] = {};
  float lrow[2][2] = {};

  for (int jt = 0; jt < 32; jt++) {
    // stage Q/V j-tile into regs (64 rows x 128B each)
    uint4 qreg[2], vreg[2];
    uint32_t soff[2];
    #pragma unroll
    for (int u = 0; u < 2; u++) {
      const int idx = tid + 256*u;        // 512 chunks
      const int row = idx >> 3, c = idx & 7;
      const uint32_t go = (uint32_t)(jt*64 + row)*128 + c*16;
      qreg[u] = *(const uint4*)(Qg + go);
      vreg[u] = *(const uint4*)(Vg + go);
      soff[u] = (uint32_t)row*128 + (uint32_t)((c ^ (row & 7)) << 4);
    }
    __syncthreads();                       // prior-iter smem reads complete
    #pragma unroll
    for (int u = 0; u < 2; u++) {
      *(uint4*)(smc + OFF_Q + soff[u]) = qreg[u];
      *(uint4*)(smc + OFF_V + soff[u]) = vreg[u];
    }
    __syncthreads();                       // Q/V visible

    // ---- S = (Kh + Kl) . Q^T ----
    float sacc[2][4][4] = {};
    #pragma unroll
    for (int ks = 0; ks < 4; ks++) {
      const int kc = 2*ks;
      uint32_t aH0[4], aH1[4], aL0[4], aL1[4], b0[4], b1[4];
      ldmat4(aH0, sKh + (uint32_t)(wr*32      + arow)*128 + (uint32_t)(((kc+achk) ^ axor) << 4));
      ldmat4(aH1, sKh + (uint32_t)(wr*32 + 16 + arow)*128 + (uint32_t)(((kc+achk) ^ axor) << 4));
      ldmat4(aL0, sKl + (uint32_t)(wr*32      + arow)*128 + (uint32_t)(((kc+achk) ^ axor) << 4));
      ldmat4(aL1, sKl + (uint32_t)(wr*32 + 16 + arow)*128 + (uint32_t)(((kc+achk) ^ axor) << 4));
      ldmat4(b0,  sQ  + (uint32_t)(wc*32      + brow)*128 + (uint32_t)(((kc+bchk) ^ bxor) << 4));
      ldmat4(b1,  sQ  + (uint32_t)(wc*32 + 16 + brow)*128 + (uint32_t)(((kc+bchk) ^ bxor) << 4));
      mma16816(sacc[0][0], aH0, b0[0], b0[1]); mma16816(sacc[0][1], aH0, b0[2], b0[3]);
      mma16816(sacc[0][2], aH0, b1[0], b1[1]); mma16816(sacc[0][3], aH0, b1[2], b1[3]);
      mma16816(sacc[1][0], aH1, b0[0], b0[1]); mma16816(sacc[1][1], aH1, b0[2], b0[3]);
      mma16816(sacc[1][2], aH1, b1[0], b1[1]); mma16816(sacc[1][3], aH1, b1[2], b1[3]);
      mma16816(sacc[0][0], aL0, b0[0], b0[1]); mma16816(sacc[0][1], aL0, b0[2], b0[3]);
      mma16816(sacc[0][2], aL0, b1[0], b1[1]); mma16816(sacc[0][3], aL0, b1[2], b1[3]);
      mma16816(sacc[1][0], aL1, b0[0], b0[1]); mma16816(sacc[1][1], aL1, b0[2], b0[3]);
      mma16816(sacc[1][2], aL1, b1[0], b1[1]); mma16816(sacc[1][3], aL1, b1[2], b1[3]);
    }

    // ---- softmax (no max) + store P hi/lo to smem ----
    #pragma unroll
    for (int mi = 0; mi < 2; mi++) {
      const int r0 = wr*32 + mi*16 + (l >> 2);
      const uint32_t rx = (uint32_t)(l >> 2) & 7;   // r0 & 7
      #pragma unroll
      for (int ni = 0; ni < 4; ni++) {
        const float p0 = __expf(sacc[mi][ni][0] * 0.125f);
        const float p1 = __expf(sacc[mi][ni][1] * 0.125f);
        const float p2 = __expf(sacc[mi][ni][2] * 0.125f);
        const float p3 = __expf(sacc[mi][ni][3] * 0.125f);
        lrow[mi][0] += p0 + p1;
        lrow[mi][1] += p2 + p3;
        const int c = wc*32 + ni*8 + 2*(l & 3);
        const uint32_t chunk = (uint32_t)(c >> 3);
        const uint32_t within = (uint32_t)(c & 7) * 2;
        const uint32_t o0 = (uint32_t)r0*128 + ((chunk ^ rx) << 4) + within;
        const uint32_t o1 = o0 + 8*128;
        const float h0 = __half2float(__float2half_rn(p0));
        const float h1 = __half2float(__float2half_rn(p1));
        const float h2 = __half2float(__float2half_rn(p2));
        const float h3 = __half2float(__float2half_rn(p3));
        *(uint32_t*)(smc + OFF_PH + o0) = pack_h2(p0, p1);
        *(uint32_t*)(smc + OFF_PH + o1) = pack_h2(p2, p3);
        *(uint32_t*)(smc + OFF_PL + o0) = pack_h2(p0 - h0, p1 - h1);
        *(uint32_t*)(smc + OFF_PL + o1) = pack_h2(p2 - h2, p3 - h3);
      }
    }
    __syncthreads();                       // P visible

    // ---- Z += (Ph + Pl) . V  (V consumed transposed via ldmatrix.trans) ----
    #pragma unroll
    for (int ks = 0; ks < 4; ks++) {
      const int kc = 2*ks;
      uint32_t pH0[4], pH1[4], pL0[4], pL1[4], v0[4], v1[4];
      ldmat4(pH0, sPh + (uint32_t)(wr*32      + arow)*128 + (uint32_t)(((kc+achk) ^ axor) << 4));
      ldmat4(pH1, sPh + (uint32_t)(wr*32 + 16 + arow)*128 + (uint32_t)(((kc+achk) ^ axor) << 4));
      ldmat4(pL0, sPl + (uint32_t)(wr*32      + arow)*128 + (uint32_t)(((kc+achk) ^ axor) << 4));
      ldmat4(pL1, sPl + (uint32_t)(wr*32 + 16 + arow)*128 + (uint32_t)(((kc+achk) ^ axor) << 4));
      const uint32_t vrowoff = (uint32_t)(16*ks + arow)*128;
      ldmat4t(v0, sV + vrowoff + (uint32_t)(((wc*4 + 0 + achk) ^ axor) << 4));
      ldmat4t(v1, sV + vrowoff + (uint32_t)(((wc*4 + 2 + achk) ^ axor) << 4));
      mma16816(zacc[0][0], pH0, v0[0], v0[1]); mma16816(zacc[0][1], pH0, v0[2], v0[3]);
      mma16816(zacc[0][2], pH0, v1[0], v1[1]); mma16816(zacc[0][3], pH0, v1[2], v1[3]);
      mma16816(zacc[1][0], pH1, v0[0], v0[1]); mma16816(zacc[1][1], pH1, v0[2], v0[3]);
      mma16816(zacc[1][2], pH1, v1[0], v1[1]); mma16816(zacc[1][3], pH1, v1[2], v1[3]);
      mma16816(zacc[0][0], pL0, v0[0], v0[1]); mma16816(zacc[0][1], pL0, v0[2], v0[3]);
      mma16816(zacc[0][2], pL0, v1[0], v1[1]); mma16816(zacc[0][3], pL0, v1[2], v1[3]);
      mma16816(zacc[1][0], pL1, v0[0], v0[1]); mma16816(zacc[1][1], pL1, v0[2], v0[3]);
      mma16816(zacc[1][2], pL1, v1[0], v1[1]); mma16816(zacc[1][3], pL1, v1[2], v1[3]);
    }
  }

  // ---- combine row sums across the two j-half warps ----
  #pragma unroll
  for (int mi = 0; mi < 2; mi++)
    #pragma unroll
    for (int h = 0; h < 2; h++) {
      float v = lrow[mi][h];
      v += __shfl_xor_sync(0xffffffffu, v, 1);
      v += __shfl_xor_sync(0xffffffffu, v, 2);
      lrow[mi][h] = v;
    }
  __syncthreads();                         // last Z-MMA smem reads done
  if ((l & 3) == 0) {
    #pragma unroll
    for (int mi = 0; mi < 2; mi++)
      #pragma unroll
      for (int h = 0; h < 2; h++)
        sL[wc*128 + wr*32 + mi*16 + h*8 + (l >> 2)] = lrow[mi][h];
  }
  __syncthreads();
  if (tid < 128) sInv[tid] = 1.f / (sL[tid] + sL[128 + tid]);
  __syncthreads();

  // ---- epilogue: Z/lsum -> g_Z ----
  float* Zg = g_Z + (size_t)g*GSZ + (size_t)it*128*64;
  #pragma unroll
  for (int mi = 0; mi < 2; mi++) {
    const int r0 = wr*32 + mi*16 + (l >> 2);
    const float inv0 = sInv[r0], inv1 = sInv[r0 + 8];
    #pragma unroll
    for (int ni = 0; ni < 4; ni++) {
      const int c = wc*32 + ni*8 + 2*(l & 3);
      *(float2*)(Zg + (size_t)r0*64 + c) =
          make_float2(zacc[mi][ni][0]*inv0, zacc[mi][ni][1]*inv0);
      *(float2*)(Zg + (size_t)(r0+8)*64 + c) =
          make_float2(zacc[mi][ni][2]*inv1, zacc[mi][ni][3]*inv1);
    }
  }
}

// ---------------------------------------------------------------------------
// GEMM3: out = Z @ Wo.  Z: (8192,768) flat, Wo: (768,64), out: (8192,64)
// ---------------------------------------------------------------------------
__global__ __launch_bounds__(256) void out_gemm(const float* __restrict__ Wo,
                                                float* __restrict__ out) {
  __shared__ float sZt[64*64];
  __shared__ float sW[64*68];
  const int mt = blockIdx.x;
  const int tid = threadIdx.x;
  const int m0 = mt*64;
  const int ty = tid >> 4, tx = tid & 15;
  float acc[4][4] = {};

  for (int kt = 0; kt < 12; kt++) {
    {
      const int i  = tid >> 2;
      const int k0 = (tid & 3) * 16;
      #pragma unroll
      for (int u = 0; u < 4; u++) {
        float4 v = *(const float4*)(g_Z + (size_t)(m0 + i)*768 + kt*64 + k0 + 4*u);
        const int k = k0 + 4*u;
        sZt[(k+0)*64 + i] = v.x; sZt[(k+1)*64 + i] = v.y;
        sZt[(k+2)*64 + i] = v.z; sZt[(k+3)*64 + i] = v.w;
      }
      const int kk = tid >> 2;
      const int j0 = (tid & 3) * 16;
      #pragma unroll
      for (int u = 0; u < 4; u++)
        *(float4*)&sW[kk*68 + j0 + 4*u] =
            *(const float4*)(Wo + (kt*64 + kk)*64 + j0 + 4*u);
    }
    __syncthreads();

    #pragma unroll 16
    for (int k = 0; k < 64; k++) {
      float4 a  = *(const float4*)&sZt[k*64 + 4*ty];
      float2 b0 = *(const float2*)&sW[k*68 + 2*tx];
      float2 b1 = *(const float2*)&sW[k*68 + 32 + 2*tx];
      float av[4] = {a.x, a.y, a.z, a.w};
      float bv[4] = {b0.x, b0.y, b1.x, b1.y};
      #pragma unroll
      for (int r = 0; r < 4; r++)
        #pragma unroll
        for (int c = 0; c < 4; c++) acc[r][c] = fmaf(av[r], bv[c], acc[r][c]);
    }
    __syncthreads();
  }

  #pragma unroll
  for (int r = 0; r < 4; r++) {
    const int mrow = m0 + 4*ty + r;
    *(float2*)(out + (size_t)mrow*64 + 2*tx)      = make_float2(acc[r][0], acc[r][1]);
    *(float2*)(out + (size_t)mrow*64 + 32 + 2*tx) = make_float2(acc[r][2], acc[r][3]);
  }
}

// ---------------------------------------------------------------------------
extern "C" void kernel_launch(void* const* d_in, const int* in_sizes, int n_in,
                              void* d_out, int out_size) {
  const float* x  = (const float*)d_in[0];
  const float* Wq = (const float*)d_in[1];
  const float* Wk = (const float*)d_in[2];
  const float* Wv = (const float*)d_in[3];
  const float* Wo = (const float*)d_in[4];
  float* out = (float*)d_out;

  qkv_gemm<<<dim3(12, 128, 3), 256>>>(x, Wq, Wk, Wv);

  cudaFuncSetAttribute(attn_mma, cudaFuncAttributeMaxDynamicSharedMemorySize,
                       SMEM_ATT);
  attn_mma<<<dim3(16, 48), 256, SMEM_ATT>>>();

  out_gemm<<<128, 256>>>(Wo, out);
}

// round 7
// speedup vs baseline: 4.2592x; 1.1094x over previous
#include <cuda_runtime.h>
#include <cuda_fp16.h>
#include <cstdint>

#define TT 2048
#define DD 64
#define NG 48
#define GSZ (TT*DD)        // 131072 elements per flat "head"

// ---- scratch (device globals; no allocation allowed) ----------------------
__device__ __half g_xh[8192*64],  g_xl[8192*64];        // x fp16 hi/lo
__device__ __half g_Wth[3*768*64], g_Wtl[3*768*64];     // W^T [mat][n][k] hi/lo
__device__ __half g_Qh[(size_t)NG*GSZ];
__device__ __half g_Kh[(size_t)NG*GSZ];
__device__ __half g_Kl[(size_t)NG*GSZ];
__device__ __half g_Vh[(size_t)NG*GSZ];
__device__ float  g_Z [(size_t)NG*GSZ];

// ---- helpers ---------------------------------------------------------------
__device__ __forceinline__ uint32_t smem_u32(const void* p) {
  uint32_t a;
  asm("{ .reg .u64 t; cvta.to.shared.u64 t, %1; cvt.u32.u64 %0, t; }"
      : "=r"(a) : "l"(p));
  return a;
}
__device__ __forceinline__ void ldmat4(uint32_t (&r)[4], uint32_t addr) {
  asm volatile("ldmatrix.sync.aligned.m8n8.x4.shared.b16 {%0,%1,%2,%3}, [%4];"
    : "=r"(r[0]), "=r"(r[1]), "=r"(r[2]), "=r"(r[3]) : "r"(addr));
}
__device__ __forceinline__ void ldmat4t(uint32_t (&r)[4], uint32_t addr) {
  asm volatile("ldmatrix.sync.aligned.m8n8.x4.trans.shared.b16 {%0,%1,%2,%3}, [%4];"
    : "=r"(r[0]), "=r"(r[1]), "=r"(r[2]), "=r"(r[3]) : "r"(addr));
}
__device__ __forceinline__ void mma16816(float (&c)[4], const uint32_t (&a)[4],
                                         uint32_t b0, uint32_t b1) {
  asm volatile("mma.sync.aligned.m16n8k16.row.col.f32.f16.f16.f32 "
    "{%0,%1,%2,%3}, {%4,%5,%6,%7}, {%8,%9}, {%0,%1,%2,%3};"
    : "+f"(c[0]), "+f"(c[1]), "+f"(c[2]), "+f"(c[3])
    : "r"(a[0]), "r"(a[1]), "r"(a[2]), "r"(a[3]), "r"(b0), "r"(b1));
}
__device__ __forceinline__ uint32_t pack_h2(float a, float b) {
  __half2 h = __floats2half2_rn(a, b);
  return *(uint32_t*)&h;
}
__device__ __forceinline__ void cpa16(uint32_t s, const void* g) {
  asm volatile("cp.async.cg.shared.global [%0], [%1], 16;" :: "r"(s), "l"(g));
}

// ---------------------------------------------------------------------------
// prep_x: x fp32 (8192x64) -> g_xh/g_xl fp16.  grid 256, block 256.
// ---------------------------------------------------------------------------
__global__ __launch_bounds__(256) void prep_x(const float* __restrict__ x) {
  const int t = blockIdx.x*256 + threadIdx.x;     // 65536 threads, 8 floats each
  const float4 v0 = *(const float4*)(x + t*8);
  const float4 v1 = *(const float4*)(x + t*8 + 4);
  const float f[8] = {v0.x, v0.y, v0.z, v0.w, v1.x, v1.y, v1.z, v1.w};
  uint32_t h[4], l[4];
  #pragma unroll
  for (int i = 0; i < 4; i++) {
    const float a = f[2*i], b = f[2*i+1];
    const float ha = __half2float(__float2half_rn(a));
    const float hb = __half2float(__float2half_rn(b));
    h[i] = pack_h2(a, b);
    l[i] = pack_h2(a - ha, b - hb);
  }
  *(uint4*)(g_xh + t*8) = make_uint4(h[0], h[1], h[2], h[3]);
  *(uint4*)(g_xl + t*8) = make_uint4(l[0], l[1], l[2], l[3]);
}

// ---------------------------------------------------------------------------
// prep_w: W (64k x 768n) fp32 -> Wt [n][k] fp16 hi/lo.  grid (12, 3), block 256.
// ---------------------------------------------------------------------------
__global__ __launch_bounds__(256) void prep_w(const float* __restrict__ Wq,
                                              const float* __restrict__ Wk,
                                              const float* __restrict__ Wv) {
  __shared__ float s[64*65];                      // [n][k]
  const int nt = blockIdx.x, mat = blockIdx.y;
  const float* W = (mat == 0) ? Wq : ((mat == 1) ? Wk : Wv);
  const int tid = threadIdx.x;
  const int n0 = nt*64;
  #pragma unroll
  for (int u = 0; u < 4; u++) {
    const int idx = tid + 256*u;                  // 1024 float4 chunks
    const int k = idx >> 4, c4 = idx & 15;
    const float4 v = *(const float4*)(W + k*768 + n0 + c4*4);
    s[(c4*4+0)*65 + k] = v.x; s[(c4*4+1)*65 + k] = v.y;
    s[(c4*4+2)*65 + k] = v.z; s[(c4*4+3)*65 + k] = v.w;
  }
  __syncthreads();
  const int n = tid >> 2, k0 = (tid & 3) * 16;
  uint32_t h[8], l[8];
  #pragma unroll
  for (int i = 0; i < 8; i++) {
    const float a = s[n*65 + k0 + 2*i], b = s[n*65 + k0 + 2*i + 1];
    const float ha = __half2float(__float2half_rn(a));
    const float hb = __half2float(__float2half_rn(b));
    h[i] = pack_h2(a, b);
    l[i] = pack_h2(a - ha, b - hb);
  }
  __half* dh = g_Wth + (size_t)(mat*768 + n0 + n)*64 + k0;
  __half* dl = g_Wtl + (size_t)(mat*768 + n0 + n)*64 + k0;
  ((uint4*)dh)[0] = make_uint4(h[0], h[1], h[2], h[3]);
  ((uint4*)dh)[1] = make_uint4(h[4], h[5], h[6], h[7]);
  ((uint4*)dl)[0] = make_uint4(l[0], l[1], l[2], l[3]);
  ((uint4*)dl)[1] = make_uint4(l[4], l[5], l[6], l[7]);
}

// ---------------------------------------------------------------------------
// qkv_mma: QKV = x @ W via HMMA, 3-term fp16 hi/lo split.
// grid (12 nt, 64 mt, 3 mat), block 256 (8 warps: 4 wr x 2 wc), tile 128m x 64n.
// Output ROW-MAJOR (8192,768); attention reinterprets flat as (48,2048,64).
// ---------------------------------------------------------------------------
#define QK_XH 0
#define QK_XL 16384
#define QK_WH 32768
#define QK_WL 40960
#define QK_SMEM 49152

__global__ __launch_bounds__(256) void qkv_mma() {
  extern __shared__ char smc[];
  const uint32_t sb = smem_u32(smc);
  const uint32_t sXh = sb + QK_XH, sXl = sb + QK_XL;
  const uint32_t sWh = sb + QK_WH, sWl = sb + QK_WL;
  const int nt = blockIdx.x, mt = blockIdx.y, mat = blockIdx.z;
  const int tid = threadIdx.x;
  const int wid = tid >> 5, l = tid & 31;
  const int wr = wid & 3, wc = wid >> 2;
  const int m0 = mt*128, n0 = nt*64;

  const int arow = (l & 7) + (((l >> 3) & 1) << 3);
  const int achk = l >> 4;
  const int brow = (l & 7) + ((l >> 4) << 3);
  const int bchk = (l >> 3) & 1;
  const int axor = l & 7, bxor = l & 7;

  // load X tile (128 rows x 128B) hi/lo, swizzled
  #pragma unroll
  for (int u = 0; u < 4; u++) {
    const int idx = tid + 256*u;                  // 1024 chunks (128 rows)
    const int row = idx >> 3, c = idx & 7;
    const uint32_t go = (uint32_t)(m0 + row)*128 + c*16;
    const uint32_t so = (uint32_t)row*128 + (uint32_t)((c ^ (row & 7)) << 4);
    *(uint4*)(smc + QK_XH + so) = *(const uint4*)((const char*)g_xh + go);
    *(uint4*)(smc + QK_XL + so) = *(const uint4*)((const char*)g_xl + go);
  }
  // load Wt tile (64 rows x 128B) hi/lo, swizzled
  #pragma unroll
  for (int u = 0; u < 2; u++) {
    const int idx = tid + 256*u;                  // 512 chunks (64 rows)
    const int row = idx >> 3, c = idx & 7;
    const uint32_t go = (uint32_t)(mat*768 + n0 + row)*128 + c*16;
    const uint32_t so = (uint32_t)row*128 + (uint32_t)((c ^ (row & 7)) << 4);
    *(uint4*)(smc + QK_WH + so) = *(const uint4*)((const char*)g_Wth + go);
    *(uint4*)(smc + QK_WL + so) = *(const uint4*)((const char*)g_Wtl + go);
  }
  __syncthreads();

  float acc[2][4][4] = {};
  #pragma unroll
  for (int ks = 0; ks < 4; ks++) {
    const int kc = 2*ks;
    uint32_t aH0[4], aH1[4], aL0[4], aL1[4], bH0[4], bH1[4], bL0[4], bL1[4];
    const uint32_t ac = (uint32_t)(((kc + achk) ^ axor) << 4);
    const uint32_t bc = (uint32_t)(((kc + bchk) ^ bxor) << 4);
    ldmat4(aH0, sXh + (uint32_t)(wr*32      + arow)*128 + ac);
    ldmat4(aH1, sXh + (uint32_t)(wr*32 + 16 + arow)*128 + ac);
    ldmat4(aL0, sXl + (uint32_t)(wr*32      + arow)*128 + ac);
    ldmat4(aL1, sXl + (uint32_t)(wr*32 + 16 + arow)*128 + ac);
    ldmat4(bH0, sWh + (uint32_t)(wc*32      + brow)*128 + bc);
    ldmat4(bH1, sWh + (uint32_t)(wc*32 + 16 + brow)*128 + bc);
    ldmat4(bL0, sWl + (uint32_t)(wc*32      + brow)*128 + bc);
    ldmat4(bL1, sWl + (uint32_t)(wc*32 + 16 + brow)*128 + bc);
    // xh*Wh
    mma16816(acc[0][0], aH0, bH0[0], bH0[1]); mma16816(acc[0][1], aH0, bH0[2], bH0[3]);
    mma16816(acc[0][2], aH0, bH1[0], bH1[1]); mma16816(acc[0][3], aH0, bH1[2], bH1[3]);
    mma16816(acc[1][0], aH1, bH0[0], bH0[1]); mma16816(acc[1][1], aH1, bH0[2], bH0[3]);
    mma16816(acc[1][2], aH1, bH1[0], bH1[1]); mma16816(acc[1][3], aH1, bH1[2], bH1[3]);
    // xh*Wl
    mma16816(acc[0][0], aH0, bL0[0], bL0[1]); mma16816(acc[0][1], aH0, bL0[2], bL0[3]);
    mma16816(acc[0][2], aH0, bL1[0], bL1[1]); mma16816(acc[0][3], aH0, bL1[2], bL1[3]);
    mma16816(acc[1][0], aH1, bL0[0], bL0[1]); mma16816(acc[1][1], aH1, bL0[2], bL0[3]);
    mma16816(acc[1][2], aH1, bL1[0], bL1[1]); mma16816(acc[1][3], aH1, bL1[2], bL1[3]);
    // xl*Wh
    mma16816(acc[0][0], aL0, bH0[0], bH0[1]); mma16816(acc[0][1], aL0, bH0[2], bH0[3]);
    mma16816(acc[0][2], aL0, bH1[0], bH1[1]); mma16816(acc[0][3], aL0, bH1[2], bH1[3]);
    mma16816(acc[1][0], aL1, bH0[0], bH0[1]); mma16816(acc[1][1], aL1, bH0[2], bH0[3]);
    mma16816(acc[1][2], aL1, bH1[0], bH1[1]); mma16816(acc[1][3], aL1, bH1[2], bH1[3]);
  }

  // epilogue: ROW-MAJOR (8192, 768)
  #pragma unroll
  for (int mi = 0; mi < 2; mi++) {
    const int r0 = wr*32 + mi*16 + (l >> 2);
    #pragma unroll
    for (int ni = 0; ni < 4; ni++) {
      const int d = wc*32 + ni*8 + 2*(l & 3);
      #pragma unroll
      for (int hh = 0; hh < 2; hh++) {
        const int r = r0 + 8*hh;
        const float a = acc[mi][ni][2*hh+0], bb = acc[mi][ni][2*hh+1];
        const size_t off = (size_t)(m0 + r)*768 + n0 + d;
        if (mat == 0) {
          *(uint32_t*)(g_Qh + off) = pack_h2(a, bb);
        } else if (mat == 1) {
          const float ha = __half2float(__float2half_rn(a));
          const float hb = __half2float(__float2half_rn(bb));
          *(uint32_t*)(g_Kh + off) = pack_h2(a, bb);
          *(uint32_t*)(g_Kl + off) = pack_h2(a - ha, bb - hb);
        } else {
          *(uint32_t*)(g_Vh + off) = pack_h2(a, bb);
        }
      }
    }
  }
}

// ---------------------------------------------------------------------------
// HMMA flash attention, cp.async double-buffered.
// grid (16 i-tiles, 48 heads), 256 threads (8 warps, 4x2).
// S = (Kh+Kl).Q^T / 8 ; no-max softmax ; Z = (Ph+Pl).V
// ---------------------------------------------------------------------------
#define OFF_KH 0
#define OFF_KL 16384
#define OFF_Q  32768     // double buffer, stride 8192
#define OFF_V  49152     // double buffer, stride 8192
#define OFF_PH 65536
#define OFF_PL 81920
#define OFF_L  98304
#define OFF_INV 99328
#define SMEM_ATT (99328 + 512)

__global__ __launch_bounds__(256, 2) void attn_mma() {
  extern __shared__ char smc[];
  const uint32_t sb = smem_u32(smc);
  const uint32_t sKh = sb + OFF_KH, sKl = sb + OFF_KL;
  const uint32_t sPh = sb + OFF_PH, sPl = sb + OFF_PL;
  float* sL   = (float*)(smc + OFF_L);
  float* sInv = (float*)(smc + OFF_INV);

  const int g = blockIdx.y, it = blockIdx.x;
  const int tid = threadIdx.x;
  const int wid = tid >> 5, l = tid & 31;
  const int wr = wid & 3, wc = wid >> 2;

  const char* Qg  = (const char*)(g_Qh + (size_t)g*GSZ);
  const char* Khg = (const char*)(g_Kh + (size_t)g*GSZ);
  const char* Klg = (const char*)(g_Kl + (size_t)g*GSZ);
  const char* Vg  = (const char*)(g_Vh + (size_t)g*GSZ);

  const int arow = (l & 7) + (((l >> 3) & 1) << 3);
  const int achk = l >> 4;
  const int brow = (l & 7) + ((l >> 4) << 3);
  const int bchk = (l >> 3) & 1;
  const int axor = l & 7, bxor = l & 7;

  // K i-tile (plain loads, once): 128 rows -> 1024 chunks
  #pragma unroll
  for (int u = 0; u < 4; u++) {
    const int idx = tid + 256*u;
    const int row = idx >> 3, c = idx & 7;
    const uint32_t go = (uint32_t)(it*128 + row)*128 + c*16;
    const uint32_t so = (uint32_t)row*128 + (uint32_t)((c ^ (row & 7)) << 4);
    *(uint4*)(smc + OFF_KH + so) = *(const uint4*)(Khg + go);
    *(uint4*)(smc + OFF_KL + so) = *(const uint4*)(Klg + go);
  }

  // prologue: prefetch jt=0 into buffer 0 (64-row tiles -> 512 chunks!)
  #pragma unroll
  for (int u = 0; u < 2; u++) {
    const int idx = tid + 256*u;
    const int row = idx >> 3, c = idx & 7;
    const uint32_t go = (uint32_t)row*128 + c*16;
    const uint32_t so = (uint32_t)row*128 + (uint32_t)((c ^ (row & 7)) << 4);
    cpa16(sb + OFF_Q + so, Qg + go);
    cpa16(sb + OFF_V + so, Vg + go);
  }
  asm volatile("cp.async.commit_group;" ::: "memory");

  float zacc[2][4][4] = {};
  float lrow[2][2] = {};

  for (int jt = 0; jt < 32; jt++) {
    const uint32_t qb = sb + OFF_Q + (uint32_t)(jt & 1)*8192;
    const uint32_t vb = sb + OFF_V + (uint32_t)(jt & 1)*8192;

    asm volatile("cp.async.wait_group 0;" ::: "memory");
    __syncthreads();      // (A) buf[cur] visible; Z(jt-1) retired

    if (jt < 31) {        // prefetch jt+1 (64-row tiles -> 512 chunks!)
      const uint32_t qn = sb + OFF_Q + (uint32_t)((jt + 1) & 1)*8192;
      const uint32_t vn = sb + OFF_V + (uint32_t)((jt + 1) & 1)*8192;
      #pragma unroll
      for (int u = 0; u < 2; u++) {
        const int idx = tid + 256*u;
        const int row = idx >> 3, c = idx & 7;
        const uint32_t go = (uint32_t)((jt + 1)*64 + row)*128 + c*16;
        const uint32_t so = (uint32_t)row*128 + (uint32_t)((c ^ (row & 7)) << 4);
        cpa16(qn + so, Qg + go);
        cpa16(vn + so, Vg + go);
      }
      asm volatile("cp.async.commit_group;" ::: "memory");
    }

    // ---- S = (Kh + Kl) . Q^T ----
    float sacc[2][4][4] = {};
    #pragma unroll
    for (int ks = 0; ks < 4; ks++) {
      const int kc = 2*ks;
      uint32_t aH0[4], aH1[4], aL0[4], aL1[4], b0[4], b1[4];
      const uint32_t ac = (uint32_t)(((kc + achk) ^ axor) << 4);
      const uint32_t bc = (uint32_t)(((kc + bchk) ^ bxor) << 4);
      ldmat4(aH0, sKh + (uint32_t)(wr*32      + arow)*128 + ac);
      ldmat4(aH1, sKh + (uint32_t)(wr*32 + 16 + arow)*128 + ac);
      ldmat4(aL0, sKl + (uint32_t)(wr*32      + arow)*128 + ac);
      ldmat4(aL1, sKl + (uint32_t)(wr*32 + 16 + arow)*128 + ac);
      ldmat4(b0,  qb  + (uint32_t)(wc*32      + brow)*128 + bc);
      ldmat4(b1,  qb  + (uint32_t)(wc*32 + 16 + brow)*128 + bc);
      mma16816(sacc[0][0], aH0, b0[0], b0[1]); mma16816(sacc[0][1], aH0, b0[2], b0[3]);
      mma16816(sacc[0][2], aH0, b1[0], b1[1]); mma16816(sacc[0][3], aH0, b1[2], b1[3]);
      mma16816(sacc[1][0], aH1, b0[0], b0[1]); mma16816(sacc[1][1], aH1, b0[2], b0[3]);
      mma16816(sacc[1][2], aH1, b1[0], b1[1]); mma16816(sacc[1][3], aH1, b1[2], b1[3]);
      mma16816(sacc[0][0], aL0, b0[0], b0[1]); mma16816(sacc[0][1], aL0, b0[2], b0[3]);
      mma16816(sacc[0][2], aL0, b1[0], b1[1]); mma16816(sacc[0][3], aL0, b1[2], b1[3]);
      mma16816(sacc[1][0], aL1, b0[0], b0[1]); mma16816(sacc[1][1], aL1, b0[2], b0[3]);
      mma16816(sacc[1][2], aL1, b1[0], b1[1]); mma16816(sacc[1][3], aL1, b1[2], b1[3]);
    }

    // ---- softmax (no max) + store P hi/lo ----
    #pragma unroll
    for (int mi = 0; mi < 2; mi++) {
      const int r0 = wr*32 + mi*16 + (l >> 2);
      const uint32_t rx = (uint32_t)(l >> 2) & 7;
      #pragma unroll
      for (int ni = 0; ni < 4; ni++) {
        const float p0 = __expf(sacc[mi][ni][0] * 0.125f);
        const float p1 = __expf(sacc[mi][ni][1] * 0.125f);
        const float p2 = __expf(sacc[mi][ni][2] * 0.125f);
        const float p3 = __expf(sacc[mi][ni][3] * 0.125f);
        lrow[mi][0] += p0 + p1;
        lrow[mi][1] += p2 + p3;
        const int c = wc*32 + ni*8 + 2*(l & 3);
        const uint32_t chunk = (uint32_t)(c >> 3);
        const uint32_t within = (uint32_t)(c & 7) * 2;
        const uint32_t o0 = (uint32_t)r0*128 + ((chunk ^ rx) << 4) + within;
        const uint32_t o1 = o0 + 8*128;
        const float h0 = __half2float(__float2half_rn(p0));
        const float h1 = __half2float(__float2half_rn(p1));
        const float h2 = __half2float(__float2half_rn(p2));
        const float h3 = __half2float(__float2half_rn(p3));
        *(uint32_t*)(smc + OFF_PH + o0) = pack_h2(p0, p1);
        *(uint32_t*)(smc + OFF_PH + o1) = pack_h2(p2, p3);
        *(uint32_t*)(smc + OFF_PL + o0) = pack_h2(p0 - h0, p1 - h1);
        *(uint32_t*)(smc + OFF_PL + o1) = pack_h2(p2 - h2, p3 - h3);
      }
    }
    __syncthreads();      // (B) P visible

    // ---- Z += (Ph + Pl) . V ----
    #pragma unroll
    for (int ks = 0; ks < 4; ks++) {
      const int kc = 2*ks;
      uint32_t pH0[4], pH1[4], pL0[4], pL1[4], v0[4], v1[4];
      const uint32_t ac = (uint32_t)(((kc + achk) ^ axor) << 4);
      ldmat4(pH0, sPh + (uint32_t)(wr*32      + arow)*128 + ac);
      ldmat4(pH1, sPh + (uint32_t)(wr*32 + 16 + arow)*128 + ac);
      ldmat4(pL0, sPl + (uint32_t)(wr*32      + arow)*128 + ac);
      ldmat4(pL1, sPl + (uint32_t)(wr*32 + 16 + arow)*128 + ac);
      const uint32_t vrowoff = (uint32_t)(16*ks + arow)*128;
      ldmat4t(v0, vb + vrowoff + (uint32_t)(((wc*4 + 0 + achk) ^ axor) << 4));
      ldmat4t(v1, vb + vrowoff + (uint32_t)(((wc*4 + 2 + achk) ^ axor) << 4));
      mma16816(zacc[0][0], pH0, v0[0], v0[1]); mma16816(zacc[0][1], pH0, v0[2], v0[3]);
      mma16816(zacc[0][2], pH0, v1[0], v1[1]); mma16816(zacc[0][3], pH0, v1[2], v1[3]);
      mma16816(zacc[1][0], pH1, v0[0], v0[1]); mma16816(zacc[1][1], pH1, v0[2], v0[3]);
      mma16816(zacc[1][2], pH1, v1[0], v1[1]); mma16816(zacc[1][3], pH1, v1[2], v1[3]);
      mma16816(zacc[0][0], pL0, v0[0], v0[1]); mma16816(zacc[0][1], pL0, v0[2], v0[3]);
      mma16816(zacc[0][2], pL0, v1[0], v1[1]); mma16816(zacc[0][3], pL0, v1[2], v1[3]);
      mma16816(zacc[1][0], pL1, v0[0], v0[1]); mma16816(zacc[1][1], pL1, v0[2], v0[3]);
      mma16816(zacc[1][2], pL1, v1[0], v1[1]); mma16816(zacc[1][3], pL1, v1[2], v1[3]);
    }
  }

  // ---- combine row sums across the two j-half warps ----
  #pragma unroll
  for (int mi = 0; mi < 2; mi++)
    #pragma unroll
    for (int h = 0; h < 2; h++) {
      float v = lrow[mi][h];
      v += __shfl_xor_sync(0xffffffffu, v, 1);
      v += __shfl_xor_sync(0xffffffffu, v, 2);
      lrow[mi][h] = v;
    }
  __syncthreads();
  if ((l & 3) == 0) {
    #pragma unroll
    for (int mi = 0; mi < 2; mi++)
      #pragma unroll
      for (int h = 0; h < 2; h++)
        sL[wc*128 + wr*32 + mi*16 + h*8 + (l >> 2)] = lrow[mi][h];
  }
  __syncthreads();
  if (tid < 128) sInv[tid] = 1.f / (sL[tid] + sL[128 + tid]);
  __syncthreads();

  // ---- epilogue: Z/lsum -> g_Z ----
  float* Zg = g_Z + (size_t)g*GSZ + (size_t)it*128*64;
  #pragma unroll
  for (int mi = 0; mi < 2; mi++) {
    const int r0 = wr*32 + mi*16 + (l >> 2);
    const float inv0 = sInv[r0], inv1 = sInv[r0 + 8];
    #pragma unroll
    for (int ni = 0; ni < 4; ni++) {
      const int c = wc*32 + ni*8 + 2*(l & 3);
      *(float2*)(Zg + (size_t)r0*64 + c) =
          make_float2(zacc[mi][ni][0]*inv0, zacc[mi][ni][1]*inv0);
      *(float2*)(Zg + (size_t)(r0+8)*64 + c) =
          make_float2(zacc[mi][ni][2]*inv1, zacc[mi][ni][3]*inv1);
    }
  }
}

// ---------------------------------------------------------------------------
// GEMM3: out = Z @ Wo.  Z: (8192,768) flat, Wo: (768,64), out: (8192,64)
// ---------------------------------------------------------------------------
__global__ __launch_bounds__(256) void out_gemm(const float* __restrict__ Wo,
                                                float* __restrict__ out) {
  __shared__ float sZt[64*64];
  __shared__ float sW[64*68];
  const int mt = blockIdx.x;
  const int tid = threadIdx.x;
  const int m0 = mt*64;
  const int ty = tid >> 4, tx = tid & 15;
  float acc[4][4] = {};

  for (int kt = 0; kt < 12; kt++) {
    {
      const int i  = tid >> 2;
      const int k0 = (tid & 3) * 16;
      #pragma unroll
      for (int u = 0; u < 4; u++) {
        float4 v = *(const float4*)(g_Z + (size_t)(m0 + i)*768 + kt*64 + k0 + 4*u);
        const int k = k0 + 4*u;
        sZt[(k+0)*64 + i] = v.x; sZt[(k+1)*64 + i] = v.y;
        sZt[(k+2)*64 + i] = v.z; sZt[(k+3)*64 + i] = v.w;
      }
      const int kk = tid >> 2;
      const int j0 = (tid & 3) * 16;
      #pragma unroll
      for (int u = 0; u < 4; u++)
        *(float4*)&sW[kk*68 + j0 + 4*u] =
            *(const float4*)(Wo + (kt*64 + kk)*64 + j0 + 4*u);
    }
    __syncthreads();

    #pragma unroll 16
    for (int k = 0; k < 64; k++) {
      float4 a  = *(const float4*)&sZt[k*64 + 4*ty];
      float2 b0 = *(const float2*)&sW[k*68 + 2*tx];
      float2 b1 = *(const float2*)&sW[k*68 + 32 + 2*tx];
      float av[4] = {a.x, a.y, a.z, a.w};
      float bv[4] = {b0.x, b0.y, b1.x, b1.y};
      #pragma unroll
      for (int r = 0; r < 4; r++)
        #pragma unroll
        for (int c = 0; c < 4; c++) acc[r][c] = fmaf(av[r], bv[c], acc[r][c]);
    }
    __syncthreads();
  }

  #pragma unroll
  for (int r = 0; r < 4; r++) {
    const int mrow = m0 + 4*ty + r;
    *(float2*)(out + (size_t)mrow*64 + 2*tx)      = make_float2(acc[r][0], acc[r][1]);
    *(float2*)(out + (size_t)mrow*64 + 32 + 2*tx) = make_float2(acc[r][2], acc[r][3]);
  }
}

// ---------------------------------------------------------------------------
extern "C" void kernel_launch(void* const* d_in, const int* in_sizes, int n_in,
                              void* d_out, int out_size) {
  const float* x  = (const float*)d_in[0];
  const float* Wq = (const float*)d_in[1];
  const float* Wk = (const float*)d_in[2];
  const float* Wv = (const float*)d_in[3];
  const float* Wo = (const float*)d_in[4];
  float* out = (float*)d_out;

  prep_x<<<256, 256>>>(x);
  prep_w<<<dim3(12, 3), 256>>>(Wq, Wk, Wv);

  cudaFuncSetAttribute(qkv_mma, cudaFuncAttributeMaxDynamicSharedMemorySize,
                       QK_SMEM);
  qkv_mma<<<dim3(12, 64, 3), 256, QK_SMEM>>>();

  cudaFuncSetAttribute(attn_mma, cudaFuncAttributeMaxDynamicSharedMemorySize,
                       SMEM_ATT);
  attn_mma<<<dim3(16, 48), 256, SMEM_ATT>>>();

  out_gemm<<<128, 256>>>(Wo, out);
}

// round 8
// speedup vs baseline: 5.7754x; 1.3560x over previous
#include <cuda_runtime.h>
#include <cuda_fp16.h>
#include <cstdint>

#define TT 2048
#define DD 64
#define NG 48
#define GSZ (TT*DD)        // 131072 elements per flat "head"

// ---- scratch (device globals; no allocation allowed) ----------------------
__device__ __half g_xh[8192*64],  g_xl[8192*64];        // x fp16 hi/lo
__device__ __half g_Wth[3*768*64], g_Wtl[3*768*64];     // W^T [mat][n][k] hi/lo
__device__ __half g_Woth[64*768], g_Wotl[64*768];       // Wo^T [n][k] hi/lo
__device__ __half g_Qh[(size_t)NG*GSZ];
__device__ __half g_Kh[(size_t)NG*GSZ];
__device__ __half g_Vh[(size_t)NG*GSZ];
__device__ __half g_Zh[(size_t)NG*GSZ];
__device__ __half g_Zl[(size_t)NG*GSZ];

// ---- helpers ---------------------------------------------------------------
__device__ __forceinline__ uint32_t smem_u32(const void* p) {
  uint32_t a;
  asm("{ .reg .u64 t; cvta.to.shared.u64 t, %1; cvt.u32.u64 %0, t; }"
      : "=r"(a) : "l"(p));
  return a;
}
__device__ __forceinline__ void ldmat4(uint32_t (&r)[4], uint32_t addr) {
  asm volatile("ldmatrix.sync.aligned.m8n8.x4.shared.b16 {%0,%1,%2,%3}, [%4];"
    : "=r"(r[0]), "=r"(r[1]), "=r"(r[2]), "=r"(r[3]) : "r"(addr));
}
__device__ __forceinline__ void ldmat4t(uint32_t (&r)[4], uint32_t addr) {
  asm volatile("ldmatrix.sync.aligned.m8n8.x4.trans.shared.b16 {%0,%1,%2,%3}, [%4];"
    : "=r"(r[0]), "=r"(r[1]), "=r"(r[2]), "=r"(r[3]) : "r"(addr));
}
__device__ __forceinline__ void mma16816(float (&c)[4], const uint32_t (&a)[4],
                                         uint32_t b0, uint32_t b1) {
  asm volatile("mma.sync.aligned.m16n8k16.row.col.f32.f16.f16.f32 "
    "{%0,%1,%2,%3}, {%4,%5,%6,%7}, {%8,%9}, {%0,%1,%2,%3};"
    : "+f"(c[0]), "+f"(c[1]), "+f"(c[2]), "+f"(c[3])
    : "r"(a[0]), "r"(a[1]), "r"(a[2]), "r"(a[3]), "r"(b0), "r"(b1));
}
__device__ __forceinline__ uint32_t pack_h2(float a, float b) {
  __half2 h = __floats2half2_rn(a, b);
  return *(uint32_t*)&h;
}
__device__ __forceinline__ void cpa16(uint32_t s, const void* g) {
  asm volatile("cp.async.cg.shared.global [%0], [%1], 16;" :: "r"(s), "l"(g));
}

// ---------------------------------------------------------------------------
// prep_x: x fp32 (8192x64) -> g_xh/g_xl fp16.  grid 256, block 256.
// ---------------------------------------------------------------------------
__global__ __launch_bounds__(256) void prep_x(const float* __restrict__ x) {
  const int t = blockIdx.x*256 + threadIdx.x;
  const float4 v0 = *(const float4*)(x + t*8);
  const float4 v1 = *(const float4*)(x + t*8 + 4);
  const float f[8] = {v0.x, v0.y, v0.z, v0.w, v1.x, v1.y, v1.z, v1.w};
  uint32_t h[4], l[4];
  #pragma unroll
  for (int i = 0; i < 4; i++) {
    const float a = f[2*i], b = f[2*i+1];
    const float ha = __half2float(__float2half_rn(a));
    const float hb = __half2float(__float2half_rn(b));
    h[i] = pack_h2(a, b);
    l[i] = pack_h2(a - ha, b - hb);
  }
  *(uint4*)(g_xh + t*8) = make_uint4(h[0], h[1], h[2], h[3]);
  *(uint4*)(g_xl + t*8) = make_uint4(l[0], l[1], l[2], l[3]);
}

// ---------------------------------------------------------------------------
// prep_w: W (64k x 768n) fp32 -> Wt [n][k] fp16 hi/lo.  grid (12, 3), block 256.
// ---------------------------------------------------------------------------
__global__ __launch_bounds__(256) void prep_w(const float* __restrict__ Wq,
                                              const float* __restrict__ Wk,
                                              const float* __restrict__ Wv) {
  __shared__ float s[64*65];                      // [n][k]
  const int nt = blockIdx.x, mat = blockIdx.y;
  const float* W = (mat == 0) ? Wq : ((mat == 1) ? Wk : Wv);
  const int tid = threadIdx.x;
  const int n0 = nt*64;
  #pragma unroll
  for (int u = 0; u < 4; u++) {
    const int idx = tid + 256*u;
    const int k = idx >> 4, c4 = idx & 15;
    const float4 v = *(const float4*)(W + k*768 + n0 + c4*4);
    s[(c4*4+0)*65 + k] = v.x; s[(c4*4+1)*65 + k] = v.y;
    s[(c4*4+2)*65 + k] = v.z; s[(c4*4+3)*65 + k] = v.w;
  }
  __syncthreads();
  const int n = tid >> 2, k0 = (tid & 3) * 16;
  uint32_t h[8], l[8];
  #pragma unroll
  for (int i = 0; i < 8; i++) {
    const float a = s[n*65 + k0 + 2*i], b = s[n*65 + k0 + 2*i + 1];
    const float ha = __half2float(__float2half_rn(a));
    const float hb = __half2float(__float2half_rn(b));
    h[i] = pack_h2(a, b);
    l[i] = pack_h2(a - ha, b - hb);
  }
  __half* dh = g_Wth + (size_t)(mat*768 + n0 + n)*64 + k0;
  __half* dl = g_Wtl + (size_t)(mat*768 + n0 + n)*64 + k0;
  ((uint4*)dh)[0] = make_uint4(h[0], h[1], h[2], h[3]);
  ((uint4*)dh)[1] = make_uint4(h[4], h[5], h[6], h[7]);
  ((uint4*)dl)[0] = make_uint4(l[0], l[1], l[2], l[3]);
  ((uint4*)dl)[1] = make_uint4(l[4], l[5], l[6], l[7]);
}

// ---------------------------------------------------------------------------
// prep_wo: Wo (768k x 64n) fp32 -> Wot [n][k] = [64][768] fp16 hi/lo.
// grid 12 (k-tiles), block 256.
// ---------------------------------------------------------------------------
__global__ __launch_bounds__(256) void prep_wo(const float* __restrict__ Wo) {
  __shared__ float s[64*65];                      // [n][k_local]
  const int kt = blockIdx.x;
  const int tid = threadIdx.x;
  const int k0g = kt*64;
  #pragma unroll
  for (int u = 0; u < 4; u++) {
    const int idx = tid + 256*u;                  // 1024 float4 chunks
    const int k = idx >> 4, c4 = idx & 15;       // k 0..63, c4 over n
    const float4 v = *(const float4*)(Wo + (size_t)(k0g + k)*64 + c4*4);
    s[(c4*4+0)*65 + k] = v.x; s[(c4*4+1)*65 + k] = v.y;
    s[(c4*4+2)*65 + k] = v.z; s[(c4*4+3)*65 + k] = v.w;
  }
  __syncthreads();
  const int n = tid >> 2, k0 = (tid & 3) * 16;
  uint32_t h[8], l[8];
  #pragma unroll
  for (int i = 0; i < 8; i++) {
    const float a = s[n*65 + k0 + 2*i], b = s[n*65 + k0 + 2*i + 1];
    const float ha = __half2float(__float2half_rn(a));
    const float hb = __half2float(__float2half_rn(b));
    h[i] = pack_h2(a, b);
    l[i] = pack_h2(a - ha, b - hb);
  }
  __half* dh = g_Woth + (size_t)n*768 + k0g + k0;
  __half* dl = g_Wotl + (size_t)n*768 + k0g + k0;
  ((uint4*)dh)[0] = make_uint4(h[0], h[1], h[2], h[3]);
  ((uint4*)dh)[1] = make_uint4(h[4], h[5], h[6], h[7]);
  ((uint4*)dl)[0] = make_uint4(l[0], l[1], l[2], l[3]);
  ((uint4*)dl)[1] = make_uint4(l[4], l[5], l[6], l[7]);
}

// ---------------------------------------------------------------------------
// qkv_mma: QKV = x @ W via HMMA, 3-term fp16 hi/lo split.
// grid (12 nt, 64 mt, 3 mat), block 256 (8 warps: 4 wr x 2 wc), tile 128m x 64n.
// Output ROW-MAJOR (8192,768); attention reinterprets flat as (48,2048,64).
// ---------------------------------------------------------------------------
#define QK_XH 0
#define QK_XL 16384
#define QK_WH 32768
#define QK_WL 40960
#define QK_SMEM 49152

__global__ __launch_bounds__(256) void qkv_mma() {
  extern __shared__ char smc[];
  const uint32_t sb = smem_u32(smc);
  const uint32_t sXh = sb + QK_XH, sXl = sb + QK_XL;
  const uint32_t sWh = sb + QK_WH, sWl = sb + QK_WL;
  const int nt = blockIdx.x, mt = blockIdx.y, mat = blockIdx.z;
  const int tid = threadIdx.x;
  const int wid = tid >> 5, l = tid & 31;
  const int wr = wid & 3, wc = wid >> 2;
  const int m0 = mt*128, n0 = nt*64;

  const int arow = (l & 7) + (((l >> 3) & 1) << 3);
  const int achk = l >> 4;
  const int brow = (l & 7) + ((l >> 4) << 3);
  const int bchk = (l >> 3) & 1;
  const int axor = l & 7, bxor = l & 7;

  #pragma unroll
  for (int u = 0; u < 4; u++) {
    const int idx = tid + 256*u;                  // 1024 chunks (128 rows)
    const int row = idx >> 3, c = idx & 7;
    const uint32_t go = (uint32_t)(m0 + row)*128 + c*16;
    const uint32_t so = (uint32_t)row*128 + (uint32_t)((c ^ (row & 7)) << 4);
    *(uint4*)(smc + QK_XH + so) = *(const uint4*)((const char*)g_xh + go);
    *(uint4*)(smc + QK_XL + so) = *(const uint4*)((const char*)g_xl + go);
  }
  #pragma unroll
  for (int u = 0; u < 2; u++) {
    const int idx = tid + 256*u;                  // 512 chunks (64 rows)
    const int row = idx >> 3, c = idx & 7;
    const uint32_t go = (uint32_t)(mat*768 + n0 + row)*128 + c*16;
    const uint32_t so = (uint32_t)row*128 + (uint32_t)((c ^ (row & 7)) << 4);
    *(uint4*)(smc + QK_WH + so) = *(const uint4*)((const char*)g_Wth + go);
    *(uint4*)(smc + QK_WL + so) = *(const uint4*)((const char*)g_Wtl + go);
  }
  __syncthreads();

  float acc[2][4][4] = {};
  #pragma unroll
  for (int ks = 0; ks < 4; ks++) {
    const int kc = 2*ks;
    uint32_t aH0[4], aH1[4], aL0[4], aL1[4], bH0[4], bH1[4], bL0[4], bL1[4];
    const uint32_t ac = (uint32_t)(((kc + achk) ^ axor) << 4);
    const uint32_t bc = (uint32_t)(((kc + bchk) ^ bxor) << 4);
    ldmat4(aH0, sXh + (uint32_t)(wr*32      + arow)*128 + ac);
    ldmat4(aH1, sXh + (uint32_t)(wr*32 + 16 + arow)*128 + ac);
    ldmat4(aL0, sXl + (uint32_t)(wr*32      + arow)*128 + ac);
    ldmat4(aL1, sXl + (uint32_t)(wr*32 + 16 + arow)*128 + ac);
    ldmat4(bH0, sWh + (uint32_t)(wc*32      + brow)*128 + bc);
    ldmat4(bH1, sWh + (uint32_t)(wc*32 + 16 + brow)*128 + bc);
    ldmat4(bL0, sWl + (uint32_t)(wc*32      + brow)*128 + bc);
    ldmat4(bL1, sWl + (uint32_t)(wc*32 + 16 + brow)*128 + bc);
    mma16816(acc[0][0], aH0, bH0[0], bH0[1]); mma16816(acc[0][1], aH0, bH0[2], bH0[3]);
    mma16816(acc[0][2], aH0, bH1[0], bH1[1]); mma16816(acc[0][3], aH0, bH1[2], bH1[3]);
    mma16816(acc[1][0], aH1, bH0[0], bH0[1]); mma16816(acc[1][1], aH1, bH0[2], bH0[3]);
    mma16816(acc[1][2], aH1, bH1[0], bH1[1]); mma16816(acc[1][3], aH1, bH1[2], bH1[3]);
    mma16816(acc[0][0], aH0, bL0[0], bL0[1]); mma16816(acc[0][1], aH0, bL0[2], bL0[3]);
    mma16816(acc[0][2], aH0, bL1[0], bL1[1]); mma16816(acc[0][3], aH0, bL1[2], bL1[3]);
    mma16816(acc[1][0], aH1, bL0[0], bL0[1]); mma16816(acc[1][1], aH1, bL0[2], bL0[3]);
    mma16816(acc[1][2], aH1, bL1[0], bL1[1]); mma16816(acc[1][3], aH1, bL1[2], bL1[3]);
    mma16816(acc[0][0], aL0, bH0[0], bH0[1]); mma16816(acc[0][1], aL0, bH0[2], bH0[3]);
    mma16816(acc[0][2], aL0, bH1[0], bH1[1]); mma16816(acc[0][3], aL0, bH1[2], bH1[3]);
    mma16816(acc[1][0], aL1, bH0[0], bH0[1]); mma16816(acc[1][1], aL1, bH0[2], bH0[3]);
    mma16816(acc[1][2], aL1, bH1[0], bH1[1]); mma16816(acc[1][3], aL1, bH1[2], bH1[3]);
  }

  #pragma unroll
  for (int mi = 0; mi < 2; mi++) {
    const int r0 = wr*32 + mi*16 + (l >> 2);
    #pragma unroll
    for (int ni = 0; ni < 4; ni++) {
      const int d = wc*32 + ni*8 + 2*(l & 3);
      #pragma unroll
      for (int hh = 0; hh < 2; hh++) {
        const int r = r0 + 8*hh;
        const float a = acc[mi][ni][2*hh+0], bb = acc[mi][ni][2*hh+1];
        const size_t off = (size_t)(m0 + r)*768 + n0 + d;
        if (mat == 0) {
          *(uint32_t*)(g_Qh + off) = pack_h2(a, bb);
        } else if (mat == 1) {
          *(uint32_t*)(g_Kh + off) = pack_h2(a, bb);
        } else {
          *(uint32_t*)(g_Vh + off) = pack_h2(a, bb);
        }
      }
    }
  }
}

// ---------------------------------------------------------------------------
// HMMA flash attention, cp.async double-buffered, pure fp16 operands.
// grid (16 i-tiles, 48 heads), 256 threads (8 warps, 4x2).
// S = K.Q^T / 8 ; no-max softmax ; Z = P.V.  Z written fp16 hi/lo.
// ---------------------------------------------------------------------------
#define OFF_KH 0         // 16KB
#define OFF_Q  16384     // double buffer, stride 8192
#define OFF_V  32768     // double buffer, stride 8192
#define OFF_PH 49152     // 16KB
#define OFF_L  65536
#define OFF_INV 66560
#define SMEM_ATT (66560 + 512)

__global__ __launch_bounds__(256, 3) void attn_mma() {
  extern __shared__ char smc[];
  const uint32_t sb = smem_u32(smc);
  const uint32_t sKh = sb + OFF_KH;
  const uint32_t sPh = sb + OFF_PH;
  float* sL   = (float*)(smc + OFF_L);
  float* sInv = (float*)(smc + OFF_INV);

  const int g = blockIdx.y, it = blockIdx.x;
  const int tid = threadIdx.x;
  const int wid = tid >> 5, l = tid & 31;
  const int wr = wid & 3, wc = wid >> 2;

  const char* Qg  = (const char*)(g_Qh + (size_t)g*GSZ);
  const char* Khg = (const char*)(g_Kh + (size_t)g*GSZ);
  const char* Vg  = (const char*)(g_Vh + (size_t)g*GSZ);

  const int arow = (l & 7) + (((l >> 3) & 1) << 3);
  const int achk = l >> 4;
  const int brow = (l & 7) + ((l >> 4) << 3);
  const int bchk = (l >> 3) & 1;
  const int axor = l & 7, bxor = l & 7;

  // K i-tile (plain loads, once): 128 rows -> 1024 chunks
  #pragma unroll
  for (int u = 0; u < 4; u++) {
    const int idx = tid + 256*u;
    const int row = idx >> 3, c = idx & 7;
    const uint32_t go = (uint32_t)(it*128 + row)*128 + c*16;
    const uint32_t so = (uint32_t)row*128 + (uint32_t)((c ^ (row & 7)) << 4);
    *(uint4*)(smc + OFF_KH + so) = *(const uint4*)(Khg + go);
  }

  // prologue: prefetch jt=0 into buffer 0 (64-row tiles -> 512 chunks)
  #pragma unroll
  for (int u = 0; u < 2; u++) {
    const int idx = tid + 256*u;
    const int row = idx >> 3, c = idx & 7;
    const uint32_t go = (uint32_t)row*128 + c*16;
    const uint32_t so = (uint32_t)row*128 + (uint32_t)((c ^ (row & 7)) << 4);
    cpa16(sb + OFF_Q + so, Qg + go);
    cpa16(sb + OFF_V + so, Vg + go);
  }
  asm volatile("cp.async.commit_group;" ::: "memory");

  float zacc[2][4][4] = {};
  float lrow[2][2] = {};

  for (int jt = 0; jt < 32; jt++) {
    const uint32_t qb = sb + OFF_Q + (uint32_t)(jt & 1)*8192;
    const uint32_t vb = sb + OFF_V + (uint32_t)(jt & 1)*8192;

    asm volatile("cp.async.wait_group 0;" ::: "memory");
    __syncthreads();      // (A) buf[cur] visible; Z(jt-1) retired

    if (jt < 31) {
      const uint32_t qn = sb + OFF_Q + (uint32_t)((jt + 1) & 1)*8192;
      const uint32_t vn = sb + OFF_V + (uint32_t)((jt + 1) & 1)*8192;
      #pragma unroll
      for (int u = 0; u < 2; u++) {
        const int idx = tid + 256*u;
        const int row = idx >> 3, c = idx & 7;
        const uint32_t go = (uint32_t)((jt + 1)*64 + row)*128 + c*16;
        const uint32_t so = (uint32_t)row*128 + (uint32_t)((c ^ (row & 7)) << 4);
        cpa16(qn + so, Qg + go);
        cpa16(vn + so, Vg + go);
      }
      asm volatile("cp.async.commit_group;" ::: "memory");
    }

    // ---- S = K . Q^T ----
    float sacc[2][4][4] = {};
    #pragma unroll
    for (int ks = 0; ks < 4; ks++) {
      const int kc = 2*ks;
      uint32_t aH0[4], aH1[4], b0[4], b1[4];
      const uint32_t ac = (uint32_t)(((kc + achk) ^ axor) << 4);
      const uint32_t bc = (uint32_t)(((kc + bchk) ^ bxor) << 4);
      ldmat4(aH0, sKh + (uint32_t)(wr*32      + arow)*128 + ac);
      ldmat4(aH1, sKh + (uint32_t)(wr*32 + 16 + arow)*128 + ac);
      ldmat4(b0,  qb  + (uint32_t)(wc*32      + brow)*128 + bc);
      ldmat4(b1,  qb  + (uint32_t)(wc*32 + 16 + brow)*128 + bc);
      mma16816(sacc[0][0], aH0, b0[0], b0[1]); mma16816(sacc[0][1], aH0, b0[2], b0[3]);
      mma16816(sacc[0][2], aH0, b1[0], b1[1]); mma16816(sacc[0][3], aH0, b1[2], b1[3]);
      mma16816(sacc[1][0], aH1, b0[0], b0[1]); mma16816(sacc[1][1], aH1, b0[2], b0[3]);
      mma16816(sacc[1][2], aH1, b1[0], b1[1]); mma16816(sacc[1][3], aH1, b1[2], b1[3]);
    }

    // ---- softmax (no max) + store P fp16 ----
    #pragma unroll
    for (int mi = 0; mi < 2; mi++) {
      const int r0 = wr*32 + mi*16 + (l >> 2);
      const uint32_t rx = (uint32_t)(l >> 2) & 7;
      #pragma unroll
      for (int ni = 0; ni < 4; ni++) {
        const float p0 = __expf(sacc[mi][ni][0] * 0.125f);
        const float p1 = __expf(sacc[mi][ni][1] * 0.125f);
        const float p2 = __expf(sacc[mi][ni][2] * 0.125f);
        const float p3 = __expf(sacc[mi][ni][3] * 0.125f);
        lrow[mi][0] += p0 + p1;
        lrow[mi][1] += p2 + p3;
        const int c = wc*32 + ni*8 + 2*(l & 3);
        const uint32_t chunk = (uint32_t)(c >> 3);
        const uint32_t within = (uint32_t)(c & 7) * 2;
        const uint32_t o0 = (uint32_t)r0*128 + ((chunk ^ rx) << 4) + within;
        const uint32_t o1 = o0 + 8*128;
        *(uint32_t*)(smc + OFF_PH + o0) = pack_h2(p0, p1);
        *(uint32_t*)(smc + OFF_PH + o1) = pack_h2(p2, p3);
      }
    }
    __syncthreads();      // (B) P visible

    // ---- Z += P . V ----
    #pragma unroll
    for (int ks = 0; ks < 4; ks++) {
      const int kc = 2*ks;
      uint32_t pH0[4], pH1[4], v0[4], v1[4];
      const uint32_t ac = (uint32_t)(((kc + achk) ^ axor) << 4);
      ldmat4(pH0, sPh + (uint32_t)(wr*32      + arow)*128 + ac);
      ldmat4(pH1, sPh + (uint32_t)(wr*32 + 16 + arow)*128 + ac);
      const uint32_t vrowoff = (uint32_t)(16*ks + arow)*128;
      ldmat4t(v0, vb + vrowoff + (uint32_t)(((wc*4 + 0 + achk) ^ axor) << 4));
      ldmat4t(v1, vb + vrowoff + (uint32_t)(((wc*4 + 2 + achk) ^ axor) << 4));
      mma16816(zacc[0][0], pH0, v0[0], v0[1]); mma16816(zacc[0][1], pH0, v0[2], v0[3]);
      mma16816(zacc[0][2], pH0, v1[0], v1[1]); mma16816(zacc[0][3], pH0, v1[2], v1[3]);
      mma16816(zacc[1][0], pH1, v0[0], v0[1]); mma16816(zacc[1][1], pH1, v0[2], v0[3]);
      mma16816(zacc[1][2], pH1, v1[0], v1[1]); mma16816(zacc[1][3], pH1, v1[2], v1[3]);
    }
  }

  // ---- combine row sums across the two j-half warps ----
  #pragma unroll
  for (int mi = 0; mi < 2; mi++)
    #pragma unroll
    for (int h = 0; h < 2; h++) {
      float v = lrow[mi][h];
      v += __shfl_xor_sync(0xffffffffu, v, 1);
      v += __shfl_xor_sync(0xffffffffu, v, 2);
      lrow[mi][h] = v;
    }
  __syncthreads();
  if ((l & 3) == 0) {
    #pragma unroll
    for (int mi = 0; mi < 2; mi++)
      #pragma unroll
      for (int h = 0; h < 2; h++)
        sL[wc*128 + wr*32 + mi*16 + h*8 + (l >> 2)] = lrow[mi][h];
  }
  __syncthreads();
  if (tid < 128) sInv[tid] = 1.f / (sL[tid] + sL[128 + tid]);
  __syncthreads();

  // ---- epilogue: Z/lsum -> g_Zh/g_Zl fp16 hi/lo ----
  __half* Zh = g_Zh + (size_t)g*GSZ + (size_t)it*128*64;
  __half* Zl = g_Zl + (size_t)g*GSZ + (size_t)it*128*64;
  #pragma unroll
  for (int mi = 0; mi < 2; mi++) {
    const int r0 = wr*32 + mi*16 + (l >> 2);
    const float inv0 = sInv[r0], inv1 = sInv[r0 + 8];
    #pragma unroll
    for (int ni = 0; ni < 4; ni++) {
      const int c = wc*32 + ni*8 + 2*(l & 3);
      const float z0 = zacc[mi][ni][0]*inv0, z1 = zacc[mi][ni][1]*inv0;
      const float z2 = zacc[mi][ni][2]*inv1, z3 = zacc[mi][ni][3]*inv1;
      const float h0 = __half2float(__float2half_rn(z0));
      const float h1 = __half2float(__float2half_rn(z1));
      const float h2 = __half2float(__float2half_rn(z2));
      const float h3 = __half2float(__float2half_rn(z3));
      *(uint32_t*)(Zh + (size_t)r0*64 + c)     = pack_h2(z0, z1);
      *(uint32_t*)(Zl + (size_t)r0*64 + c)     = pack_h2(z0 - h0, z1 - h1);
      *(uint32_t*)(Zh + (size_t)(r0+8)*64 + c) = pack_h2(z2, z3);
      *(uint32_t*)(Zl + (size_t)(r0+8)*64 + c) = pack_h2(z2 - h2, z3 - h3);
    }
  }
}

// ---------------------------------------------------------------------------
// out_mma: out = Z @ Wo via HMMA, 3-term split (Zh*Wh + Zh*Wl + Zl*Wh).
// Z flat (8192,768) fp16 hi/lo; Wot [64][768] fp16 hi/lo; out (8192,64) fp32.
// grid 64 (mt), block 256 (8 warps 4x2), tile 128m x 64n, 12 k-chunks of 64.
// ---------------------------------------------------------------------------
#define OG_ZH 0
#define OG_ZL 16384
#define OG_WH 32768
#define OG_WL 40960
#define OG_SMEM 49152

__global__ __launch_bounds__(256) void out_mma(float* __restrict__ out) {
  extern __shared__ char smc[];
  const uint32_t sb = smem_u32(smc);
  const uint32_t sZh = sb + OG_ZH, sZl = sb + OG_ZL;
  const uint32_t sWh = sb + OG_WH, sWl = sb + OG_WL;
  const int mt = blockIdx.x;
  const int tid = threadIdx.x;
  const int wid = tid >> 5, l = tid & 31;
  const int wr = wid & 3, wc = wid >> 2;
  const int m0 = mt*128;

  const int arow = (l & 7) + (((l >> 3) & 1) << 3);
  const int achk = l >> 4;
  const int brow = (l & 7) + ((l >> 4) << 3);
  const int bchk = (l >> 3) & 1;
  const int axor = l & 7, bxor = l & 7;

  float acc[2][4][4] = {};

  for (int kt = 0; kt < 12; kt++) {
    // Z tile: 128 rows x 64 k (=128B) hi/lo
    #pragma unroll
    for (int u = 0; u < 4; u++) {
      const int idx = tid + 256*u;                // 1024 chunks
      const int row = idx >> 3, c = idx & 7;
      const uint32_t go = (uint32_t)(m0 + row)*1536 + (uint32_t)kt*128 + c*16;
      const uint32_t so = (uint32_t)row*128 + (uint32_t)((c ^ (row & 7)) << 4);
      *(uint4*)(smc + OG_ZH + so) = *(const uint4*)((const char*)g_Zh + go);
      *(uint4*)(smc + OG_ZL + so) = *(const uint4*)((const char*)g_Zl + go);
    }
    // W tile: 64 n-rows x 64 k (=128B) hi/lo
    #pragma unroll
    for (int u = 0; u < 2; u++) {
      const int idx = tid + 256*u;                // 512 chunks
      const int row = idx >> 3, c = idx & 7;
      const uint32_t go = (uint32_t)row*1536 + (uint32_t)kt*128 + c*16;
      const uint32_t so = (uint32_t)row*128 + (uint32_t)((c ^ (row & 7)) << 4);
      *(uint4*)(smc + OG_WH + so) = *(const uint4*)((const char*)g_Woth + go);
      *(uint4*)(smc + OG_WL + so) = *(const uint4*)((const char*)g_Wotl + go);
    }
    __syncthreads();

    #pragma unroll
    for (int ks = 0; ks < 4; ks++) {
      const int kc = 2*ks;
      uint32_t aH0[4], aH1[4], aL0[4], aL1[4], bH0[4], bH1[4], bL0[4], bL1[4];
      const uint32_t ac = (uint32_t)(((kc + achk) ^ axor) << 4);
      const uint32_t bc = (uint32_t)(((kc + bchk) ^ bxor) << 4);
      ldmat4(aH0, sZh + (uint32_t)(wr*32      + arow)*128 + ac);
      ldmat4(aH1, sZh + (uint32_t)(wr*32 + 16 + arow)*128 + ac);
      ldmat4(aL0, sZl + (uint32_t)(wr*32      + arow)*128 + ac);
      ldmat4(aL1, sZl + (uint32_t)(wr*32 + 16 + arow)*128 + ac);
      ldmat4(bH0, sWh + (uint32_t)(wc*32      + brow)*128 + bc);
      ldmat4(bH1, sWh + (uint32_t)(wc*32 + 16 + brow)*128 + bc);
      ldmat4(bL0, sWl + (uint32_t)(wc*32      + brow)*128 + bc);
      ldmat4(bL1, sWl + (uint32_t)(wc*32 + 16 + brow)*128 + bc);
      mma16816(acc[0][0], aH0, bH0[0], bH0[1]); mma16816(acc[0][1], aH0, bH0[2], bH0[3]);
      mma16816(acc[0][2], aH0, bH1[0], bH1[1]); mma16816(acc[0][3], aH0, bH1[2], bH1[3]);
      mma16816(acc[1][0], aH1, bH0[0], bH0[1]); mma16816(acc[1][1], aH1, bH0[2], bH0[3]);
      mma16816(acc[1][2], aH1, bH1[0], bH1[1]); mma16816(acc[1][3], aH1, bH1[2], bH1[3]);
      mma16816(acc[0][0], aH0, bL0[0], bL0[1]); mma16816(acc[0][1], aH0, bL0[2], bL0[3]);
      mma16816(acc[0][2], aH0, bL1[0], bL1[1]); mma16816(acc[0][3], aH0, bL1[2], bL1[3]);
      mma16816(acc[1][0], aH1, bL0[0], bL0[1]); mma16816(acc[1][1], aH1, bL0[2], bL0[3]);
      mma16816(acc[1][2], aH1, bL1[0], bL1[1]); mma16816(acc[1][3], aH1, bL1[2], bL1[3]);
      mma16816(acc[0][0], aL0, bH0[0], bH0[1]); mma16816(acc[0][1], aL0, bH0[2], bH0[3]);
      mma16816(acc[0][2], aL0, bH1[0], bH1[1]); mma16816(acc[0][3], aL0, bH1[2], bH1[3]);
      mma16816(acc[1][0], aL1, bH0[0], bH0[1]); mma16816(acc[1][1], aL1, bH0[2], bH0[3]);
      mma16816(acc[1][2], aL1, bH1[0], bH1[1]); mma16816(acc[1][3], aL1, bH1[2], bH1[3]);
    }
    __syncthreads();
  }

  // epilogue: out (8192,64) fp32
  #pragma unroll
  for (int mi = 0; mi < 2; mi++) {
    const int r0 = wr*32 + mi*16 + (l >> 2);
    #pragma unroll
    for (int ni = 0; ni < 4; ni++) {
      const int n = wc*32 + ni*8 + 2*(l & 3);
      *(float2*)(out + (size_t)(m0 + r0)*64 + n) =
          make_float2(acc[mi][ni][0], acc[mi][ni][1]);
      *(float2*)(out + (size_t)(m0 + r0 + 8)*64 + n) =
          make_float2(acc[mi][ni][2], acc[mi][ni][3]);
    }
  }
}

// ---------------------------------------------------------------------------
extern "C" void kernel_launch(void* const* d_in, const int* in_sizes, int n_in,
                              void* d_out, int out_size) {
  const float* x  = (const float*)d_in[0];
  const float* Wq = (const float*)d_in[1];
  const float* Wk = (const float*)d_in[2];
  const float* Wv = (const float*)d_in[3];
  const float* Wo = (const float*)d_in[4];
  float* out = (float*)d_out;

  prep_x<<<256, 256>>>(x);
  prep_w<<<dim3(12, 3), 256>>>(Wq, Wk, Wv);
  prep_wo<<<12, 256>>>(Wo);

  cudaFuncSetAttribute(qkv_mma, cudaFuncAttributeMaxDynamicSharedMemorySize,
                       QK_SMEM);
  qkv_mma<<<dim3(12, 64, 3), 256, QK_SMEM>>>();

  cudaFuncSetAttribute(attn_mma, cudaFuncAttributeMaxDynamicSharedMemorySize,
                       SMEM_ATT);
  attn_mma<<<dim3(16, 48), 256, SMEM_ATT>>>();

  cudaFuncSetAttribute(out_mma, cudaFuncAttributeMaxDynamicSharedMemorySize,
                       OG_SMEM);
  out_mma<<<64, 256, OG_SMEM>>>(out);
}

// round 9
// speedup vs baseline: 7.5370x; 1.3050x over previous
#include <cuda_runtime.h>
#include <cuda_fp16.h>
#include <cstdint>

#define TT 2048
#define DD 64
#define NG 48
#define GSZ (TT*DD)        // 131072 elements per flat "head"

// ---- scratch (device globals; no allocation allowed) ----------------------
__device__ __half g_xh[8192*64],  g_xl[8192*64];        // x fp16 hi/lo
__device__ __half g_Wth[3*768*64], g_Wtl[3*768*64];     // W^T [mat][n][k] hi/lo
__device__ __half g_Woth[64*768], g_Wotl[64*768];       // Wo^T [n][k] hi/lo
__device__ __half g_Qh[(size_t)NG*GSZ];
__device__ __half g_Kh[(size_t)NG*GSZ];
__device__ __half g_Vh[(size_t)NG*GSZ];
__device__ __half g_Zh[(size_t)NG*GSZ];
__device__ __half g_Zl[(size_t)NG*GSZ];

// ---- helpers ---------------------------------------------------------------
__device__ __forceinline__ uint32_t smem_u32(const void* p) {
  uint32_t a;
  asm("{ .reg .u64 t; cvta.to.shared.u64 t, %1; cvt.u32.u64 %0, t; }"
      : "=r"(a) : "l"(p));
  return a;
}
__device__ __forceinline__ void ldmat4(uint32_t (&r)[4], uint32_t addr) {
  asm volatile("ldmatrix.sync.aligned.m8n8.x4.shared.b16 {%0,%1,%2,%3}, [%4];"
    : "=r"(r[0]), "=r"(r[1]), "=r"(r[2]), "=r"(r[3]) : "r"(addr));
}
__device__ __forceinline__ void ldmat4t(uint32_t (&r)[4], uint32_t addr) {
  asm volatile("ldmatrix.sync.aligned.m8n8.x4.trans.shared.b16 {%0,%1,%2,%3}, [%4];"
    : "=r"(r[0]), "=r"(r[1]), "=r"(r[2]), "=r"(r[3]) : "r"(addr));
}
__device__ __forceinline__ void mma16816(float (&c)[4], const uint32_t (&a)[4],
                                         uint32_t b0, uint32_t b1) {
  asm volatile("mma.sync.aligned.m16n8k16.row.col.f32.f16.f16.f32 "
    "{%0,%1,%2,%3}, {%4,%5,%6,%7}, {%8,%9}, {%0,%1,%2,%3};"
    : "+f"(c[0]), "+f"(c[1]), "+f"(c[2]), "+f"(c[3])
    : "r"(a[0]), "r"(a[1]), "r"(a[2]), "r"(a[3]), "r"(b0), "r"(b1));
}
__device__ __forceinline__ uint32_t pack_h2(float a, float b) {
  __half2 h = __floats2half2_rn(a, b);
  return *(uint32_t*)&h;
}
__device__ __forceinline__ void cpa16(uint32_t s, const void* g) {
  asm volatile("cp.async.cg.shared.global [%0], [%1], 16;" :: "r"(s), "l"(g));
}

// ---------------------------------------------------------------------------
// prep_x: x fp32 (8192x64) -> g_xh/g_xl fp16.  grid 256, block 256.
// ---------------------------------------------------------------------------
__global__ __launch_bounds__(256) void prep_x(const float* __restrict__ x) {
  const int t = blockIdx.x*256 + threadIdx.x;
  const float4 v0 = *(const float4*)(x + t*8);
  const float4 v1 = *(const float4*)(x + t*8 + 4);
  const float f[8] = {v0.x, v0.y, v0.z, v0.w, v1.x, v1.y, v1.z, v1.w};
  uint32_t h[4], l[4];
  #pragma unroll
  for (int i = 0; i < 4; i++) {
    const float a = f[2*i], b = f[2*i+1];
    const float ha = __half2float(__float2half_rn(a));
    const float hb = __half2float(__float2half_rn(b));
    h[i] = pack_h2(a, b);
    l[i] = pack_h2(a - ha, b - hb);
  }
  *(uint4*)(g_xh + t*8) = make_uint4(h[0], h[1], h[2], h[3]);
  *(uint4*)(g_xl + t*8) = make_uint4(l[0], l[1], l[2], l[3]);
}

// ---------------------------------------------------------------------------
// prep_w: W (64k x 768n) fp32 -> Wt [n][k] fp16 hi/lo.  grid (12, 3), block 256.
// ---------------------------------------------------------------------------
__global__ __launch_bounds__(256) void prep_w(const float* __restrict__ Wq,
                                              const float* __restrict__ Wk,
                                              const float* __restrict__ Wv) {
  __shared__ float s[64*65];
  const int nt = blockIdx.x, mat = blockIdx.y;
  const float* W = (mat == 0) ? Wq : ((mat == 1) ? Wk : Wv);
  const int tid = threadIdx.x;
  const int n0 = nt*64;
  #pragma unroll
  for (int u = 0; u < 4; u++) {
    const int idx = tid + 256*u;
    const int k = idx >> 4, c4 = idx & 15;
    const float4 v = *(const float4*)(W + k*768 + n0 + c4*4);
    s[(c4*4+0)*65 + k] = v.x; s[(c4*4+1)*65 + k] = v.y;
    s[(c4*4+2)*65 + k] = v.z; s[(c4*4+3)*65 + k] = v.w;
  }
  __syncthreads();
  const int n = tid >> 2, k0 = (tid & 3) * 16;
  uint32_t h[8], l[8];
  #pragma unroll
  for (int i = 0; i < 8; i++) {
    const float a = s[n*65 + k0 + 2*i], b = s[n*65 + k0 + 2*i + 1];
    const float ha = __half2float(__float2half_rn(a));
    const float hb = __half2float(__float2half_rn(b));
    h[i] = pack_h2(a, b);
    l[i] = pack_h2(a - ha, b - hb);
  }
  __half* dh = g_Wth + (size_t)(mat*768 + n0 + n)*64 + k0;
  __half* dl = g_Wtl + (size_t)(mat*768 + n0 + n)*64 + k0;
  ((uint4*)dh)[0] = make_uint4(h[0], h[1], h[2], h[3]);
  ((uint4*)dh)[1] = make_uint4(h[4], h[5], h[6], h[7]);
  ((uint4*)dl)[0] = make_uint4(l[0], l[1], l[2], l[3]);
  ((uint4*)dl)[1] = make_uint4(l[4], l[5], l[6], l[7]);
}

// ---------------------------------------------------------------------------
// prep_wo: Wo (768k x 64n) fp32 -> Wot [64][768] fp16 hi/lo.  grid 12, block 256.
// ---------------------------------------------------------------------------
__global__ __launch_bounds__(256) void prep_wo(const float* __restrict__ Wo) {
  __shared__ float s[64*65];
  const int kt = blockIdx.x;
  const int tid = threadIdx.x;
  const int k0g = kt*64;
  #pragma unroll
  for (int u = 0; u < 4; u++) {
    const int idx = tid + 256*u;
    const int k = idx >> 4, c4 = idx & 15;
    const float4 v = *(const float4*)(Wo + (size_t)(k0g + k)*64 + c4*4);
    s[(c4*4+0)*65 + k] = v.x; s[(c4*4+1)*65 + k] = v.y;
    s[(c4*4+2)*65 + k] = v.z; s[(c4*4+3)*65 + k] = v.w;
  }
  __syncthreads();
  const int n = tid >> 2, k0 = (tid & 3) * 16;
  uint32_t h[8], l[8];
  #pragma unroll
  for (int i = 0; i < 8; i++) {
    const float a = s[n*65 + k0 + 2*i], b = s[n*65 + k0 + 2*i + 1];
    const float ha = __half2float(__float2half_rn(a));
    const float hb = __half2float(__float2half_rn(b));
    h[i] = pack_h2(a, b);
    l[i] = pack_h2(a - ha, b - hb);
  }
  __half* dh = g_Woth + (size_t)n*768 + k0g + k0;
  __half* dl = g_Wotl + (size_t)n*768 + k0g + k0;
  ((uint4*)dh)[0] = make_uint4(h[0], h[1], h[2], h[3]);
  ((uint4*)dh)[1] = make_uint4(h[4], h[5], h[6], h[7]);
  ((uint4*)dl)[0] = make_uint4(l[0], l[1], l[2], l[3]);
  ((uint4*)dl)[1] = make_uint4(l[4], l[5], l[6], l[7]);
}

// ---------------------------------------------------------------------------
// qkv_mma: QKV = x @ W via HMMA, 3-term fp16 hi/lo split.
// grid (12 nt, 64 mt, 3 mat), block 256, tile 128m x 64n.  (unchanged)
// ---------------------------------------------------------------------------
#define QK_XH 0
#define QK_XL 16384
#define QK_WH 32768
#define QK_WL 40960
#define QK_SMEM 49152

__global__ __launch_bounds__(256) void qkv_mma() {
  extern __shared__ char smc[];
  const uint32_t sb = smem_u32(smc);
  const uint32_t sXh = sb + QK_XH, sXl = sb + QK_XL;
  const uint32_t sWh = sb + QK_WH, sWl = sb + QK_WL;
  const int nt = blockIdx.x, mt = blockIdx.y, mat = blockIdx.z;
  const int tid = threadIdx.x;
  const int wid = tid >> 5, l = tid & 31;
  const int wr = wid & 3, wc = wid >> 2;
  const int m0 = mt*128, n0 = nt*64;

  const int arow = (l & 7) + (((l >> 3) & 1) << 3);
  const int achk = l >> 4;
  const int brow = (l & 7) + ((l >> 4) << 3);
  const int bchk = (l >> 3) & 1;
  const int axor = l & 7, bxor = l & 7;

  #pragma unroll
  for (int u = 0; u < 4; u++) {
    const int idx = tid + 256*u;
    const int row = idx >> 3, c = idx & 7;
    const uint32_t go = (uint32_t)(m0 + row)*128 + c*16;
    const uint32_t so = (uint32_t)row*128 + (uint32_t)((c ^ (row & 7)) << 4);
    *(uint4*)(smc + QK_XH + so) = *(const uint4*)((const char*)g_xh + go);
    *(uint4*)(smc + QK_XL + so) = *(const uint4*)((const char*)g_xl + go);
  }
  #pragma unroll
  for (int u = 0; u < 2; u++) {
    const int idx = tid + 256*u;
    const int row = idx >> 3, c = idx & 7;
    const uint32_t go = (uint32_t)(mat*768 + n0 + row)*128 + c*16;
    const uint32_t so = (uint32_t)row*128 + (uint32_t)((c ^ (row & 7)) << 4);
    *(uint4*)(smc + QK_WH + so) = *(const uint4*)((const char*)g_Wth + go);
    *(uint4*)(smc + QK_WL + so) = *(const uint4*)((const char*)g_Wtl + go);
  }
  __syncthreads();

  float acc[2][4][4] = {};
  #pragma unroll
  for (int ks = 0; ks < 4; ks++) {
    const int kc = 2*ks;
    uint32_t aH0[4], aH1[4], aL0[4], aL1[4], bH0[4], bH1[4], bL0[4], bL1[4];
    const uint32_t ac = (uint32_t)(((kc + achk) ^ axor) << 4);
    const uint32_t bc = (uint32_t)(((kc + bchk) ^ bxor) << 4);
    ldmat4(aH0, sXh + (uint32_t)(wr*32      + arow)*128 + ac);
    ldmat4(aH1, sXh + (uint32_t)(wr*32 + 16 + arow)*128 + ac);
    ldmat4(aL0, sXl + (uint32_t)(wr*32      + arow)*128 + ac);
    ldmat4(aL1, sXl + (uint32_t)(wr*32 + 16 + arow)*128 + ac);
    ldmat4(bH0, sWh + (uint32_t)(wc*32      + brow)*128 + bc);
    ldmat4(bH1, sWh + (uint32_t)(wc*32 + 16 + brow)*128 + bc);
    ldmat4(bL0, sWl + (uint32_t)(wc*32      + brow)*128 + bc);
    ldmat4(bL1, sWl + (uint32_t)(wc*32 + 16 + brow)*128 + bc);
    mma16816(acc[0][0], aH0, bH0[0], bH0[1]); mma16816(acc[0][1], aH0, bH0[2], bH0[3]);
    mma16816(acc[0][2], aH0, bH1[0], bH1[1]); mma16816(acc[0][3], aH0, bH1[2], bH1[3]);
    mma16816(acc[1][0], aH1, bH0[0], bH0[1]); mma16816(acc[1][1], aH1, bH0[2], bH0[3]);
    mma16816(acc[1][2], aH1, bH1[0], bH1[1]); mma16816(acc[1][3], aH1, bH1[2], bH1[3]);
    mma16816(acc[0][0], aH0, bL0[0], bL0[1]); mma16816(acc[0][1], aH0, bL0[2], bL0[3]);
    mma16816(acc[0][2], aH0, bL1[0], bL1[1]); mma16816(acc[0][3], aH0, bL1[2], bL1[3]);
    mma16816(acc[1][0], aH1, bL0[0], bL0[1]); mma16816(acc[1][1], aH1, bL0[2], bL0[3]);
    mma16816(acc[1][2], aH1, bL1[0], bL1[1]); mma16816(acc[1][3], aH1, bL1[2], bL1[3]);
    mma16816(acc[0][0], aL0, bH0[0], bH0[1]); mma16816(acc[0][1], aL0, bH0[2], bH0[3]);
    mma16816(acc[0][2], aL0, bH1[0], bH1[1]); mma16816(acc[0][3], aL0, bH1[2], bH1[3]);
    mma16816(acc[1][0], aL1, bH0[0], bH0[1]); mma16816(acc[1][1], aL1, bH0[2], bH0[3]);
    mma16816(acc[1][2], aL1, bH1[0], bH1[1]); mma16816(acc[1][3], aL1, bH1[2], bH1[3]);
  }

  #pragma unroll
  for (int mi = 0; mi < 2; mi++) {
    const int r0 = wr*32 + mi*16 + (l >> 2);
    #pragma unroll
    for (int ni = 0; ni < 4; ni++) {
      const int d = wc*32 + ni*8 + 2*(l & 3);
      #pragma unroll
      for (int hh = 0; hh < 2; hh++) {
        const int r = r0 + 8*hh;
        const float a = acc[mi][ni][2*hh+0], bb = acc[mi][ni][2*hh+1];
        const size_t off = (size_t)(m0 + r)*768 + n0 + d;
        if (mat == 0) {
          *(uint32_t*)(g_Qh + off) = pack_h2(a, bb);
        } else if (mat == 1) {
          *(uint32_t*)(g_Kh + off) = pack_h2(a, bb);
        } else {
          *(uint32_t*)(g_Vh + off) = pack_h2(a, bb);
        }
      }
    }
  }
}

// ---------------------------------------------------------------------------
// HMMA flash attention, register-resident P (FA2 fragment reuse).
// grid (16 i-tiles, 48 heads), 256 threads = 8 warps; warp w owns i rows
// [w*16, w*16+16).  S C-frag -> P A-frag in registers; 1 barrier per j-tile;
// per-warp row sums (no cross-warp combine).  Z written fp16 hi/lo.
// ---------------------------------------------------------------------------
#define OFF_KH 0         // 16KB
#define OFF_Q  16384     // double buffer, stride 8192
#define OFF_V  32768     // double buffer, stride 8192
#define SMEM_ATT 49152

__global__ __launch_bounds__(256, 2) void attn_mma() {
  extern __shared__ char smc[];
  const uint32_t sb = smem_u32(smc);
  const uint32_t sKh = sb + OFF_KH;

  const int g = blockIdx.y, it = blockIdx.x;
  const int tid = threadIdx.x;
  const int w = tid >> 5, l = tid & 31;

  const char* Qg  = (const char*)(g_Qh + (size_t)g*GSZ);
  const char* Khg = (const char*)(g_Kh + (size_t)g*GSZ);
  const char* Vg  = (const char*)(g_Vh + (size_t)g*GSZ);

  const int arow = (l & 7) + (((l >> 3) & 1) << 3);
  const int achk = l >> 4;
  const int brow = (l & 7) + ((l >> 4) << 3);
  const int bchk = (l >> 3) & 1;
  const int axor = l & 7, bxor = l & 7;

  // K i-tile (plain loads, once): 128 rows -> 1024 chunks
  #pragma unroll
  for (int u = 0; u < 4; u++) {
    const int idx = tid + 256*u;
    const int row = idx >> 3, c = idx & 7;
    const uint32_t go = (uint32_t)(it*128 + row)*128 + c*16;
    const uint32_t so = (uint32_t)row*128 + (uint32_t)((c ^ (row & 7)) << 4);
    *(uint4*)(smc + OFF_KH + so) = *(const uint4*)(Khg + go);
  }

  // prologue: prefetch jt=0 into buffer 0 (64-row tiles -> 512 chunks)
  #pragma unroll
  for (int u = 0; u < 2; u++) {
    const int idx = tid + 256*u;
    const int row = idx >> 3, c = idx & 7;
    const uint32_t go = (uint32_t)row*128 + c*16;
    const uint32_t so = (uint32_t)row*128 + (uint32_t)((c ^ (row & 7)) << 4);
    cpa16(sb + OFF_Q + so, Qg + go);
    cpa16(sb + OFF_V + so, Vg + go);
  }
  asm volatile("cp.async.commit_group;" ::: "memory");

  float zacc[8][4] = {};
  float lrow[2] = {0.f, 0.f};

  for (int jt = 0; jt < 32; jt++) {
    const uint32_t qb = sb + OFF_Q + (uint32_t)(jt & 1)*8192;
    const uint32_t vb = sb + OFF_V + (uint32_t)(jt & 1)*8192;

    asm volatile("cp.async.wait_group 0;" ::: "memory");
    __syncthreads();      // buf[cur] visible; all warps done with jt-1

    if (jt < 31) {
      const uint32_t qn = sb + OFF_Q + (uint32_t)((jt + 1) & 1)*8192;
      const uint32_t vn = sb + OFF_V + (uint32_t)((jt + 1) & 1)*8192;
      #pragma unroll
      for (int u = 0; u < 2; u++) {
        const int idx = tid + 256*u;
        const int row = idx >> 3, c = idx & 7;
        const uint32_t go = (uint32_t)((jt + 1)*64 + row)*128 + c*16;
        const uint32_t so = (uint32_t)row*128 + (uint32_t)((c ^ (row & 7)) << 4);
        cpa16(qn + so, Qg + go);
        cpa16(vn + so, Vg + go);
      }
      asm volatile("cp.async.commit_group;" ::: "memory");
    }

    // ---- S = K . Q^T  (m16 per warp, n = 64 j in 8 tiles) ----
    float sacc[8][4] = {};
    #pragma unroll
    for (int ks = 0; ks < 4; ks++) {
      const int kc = 2*ks;
      uint32_t a[4];
      const uint32_t ac = (uint32_t)(((kc + achk) ^ axor) << 4);
      const uint32_t bc = (uint32_t)(((kc + bchk) ^ bxor) << 4);
      ldmat4(a, sKh + (uint32_t)(w*16 + arow)*128 + ac);
      #pragma unroll
      for (int jb = 0; jb < 4; jb++) {
        uint32_t q[4];
        ldmat4(q, qb + (uint32_t)(jb*16 + brow)*128 + bc);
        mma16816(sacc[2*jb],   a, q[0], q[1]);
        mma16816(sacc[2*jb+1], a, q[2], q[3]);
      }
    }

    // ---- softmax (no max) in registers; P packed as A-fragments ----
    uint32_t pa[8], pb[8];
    #pragma unroll
    for (int nt = 0; nt < 8; nt++) {
      const float p0 = __expf(sacc[nt][0] * 0.125f);
      const float p1 = __expf(sacc[nt][1] * 0.125f);
      const float p2 = __expf(sacc[nt][2] * 0.125f);
      const float p3 = __expf(sacc[nt][3] * 0.125f);
      lrow[0] += p0 + p1;
      lrow[1] += p2 + p3;
      pa[nt] = pack_h2(p0, p1);
      pb[nt] = pack_h2(p2, p3);
    }

    // ---- Z += P . V  (k = 64 j in 4 chunks, n = 64 d in 8 tiles) ----
    #pragma unroll
    for (int kj = 0; kj < 4; kj++) {
      const uint32_t A[4] = {pa[2*kj], pb[2*kj], pa[2*kj+1], pb[2*kj+1]};
      #pragma unroll
      for (int d4 = 0; d4 < 4; d4++) {
        uint32_t v[4];
        ldmat4t(v, vb + (uint32_t)(16*kj + arow)*128 +
                   (uint32_t)(((2*d4 + achk) ^ axor) << 4));
        mma16816(zacc[2*d4],   A, v[0], v[1]);
        mma16816(zacc[2*d4+1], A, v[2], v[3]);
      }
    }
  }

  // ---- final row sums (within quad) and epilogue ----
  #pragma unroll
  for (int h = 0; h < 2; h++) {
    float v = lrow[h];
    v += __shfl_xor_sync(0xffffffffu, v, 1);
    v += __shfl_xor_sync(0xffffffffu, v, 2);
    lrow[h] = v;
  }
  const float inv0 = 1.f / lrow[0];
  const float inv1 = 1.f / lrow[1];

  __half* Zh = g_Zh + (size_t)g*GSZ + (size_t)it*128*64;
  __half* Zl = g_Zl + (size_t)g*GSZ + (size_t)it*128*64;
  const int r0 = w*16 + (l >> 2);
  #pragma unroll
  for (int nt = 0; nt < 8; nt++) {
    const int c = nt*8 + 2*(l & 3);
    const float z0 = zacc[nt][0]*inv0, z1 = zacc[nt][1]*inv0;
    const float z2 = zacc[nt][2]*inv1, z3 = zacc[nt][3]*inv1;
    const float h0 = __half2float(__float2half_rn(z0));
    const float h1 = __half2float(__float2half_rn(z1));
    const float h2 = __half2float(__float2half_rn(z2));
    const float h3 = __half2float(__float2half_rn(z3));
    *(uint32_t*)(Zh + (size_t)r0*64 + c)     = pack_h2(z0, z1);
    *(uint32_t*)(Zl + (size_t)r0*64 + c)     = pack_h2(z0 - h0, z1 - h1);
    *(uint32_t*)(Zh + (size_t)(r0+8)*64 + c) = pack_h2(z2, z3);
    *(uint32_t*)(Zl + (size_t)(r0+8)*64 + c) = pack_h2(z2 - h2, z3 - h3);
  }
}

// ---------------------------------------------------------------------------
// out_mma: out = Z @ Wo via HMMA, 3-term split, cp.async double-buffered.
// grid 128 (m-tile 64), block 256 (8 warps 4x2: wr m16, wc n32), 12 k-chunks.
// ---------------------------------------------------------------------------
#define OG_ZH 0          // double buffer, stride 8192
#define OG_ZL 16384      // double buffer, stride 8192
#define OG_WH 32768      // double buffer, stride 8192
#define OG_WL 49152      // double buffer, stride 8192
#define OG_SMEM 65536

__global__ __launch_bounds__(256) void out_mma(float* __restrict__ out) {
  extern __shared__ char smc[];
  const uint32_t sb = smem_u32(smc);
  const int mt = blockIdx.x;
  const int tid = threadIdx.x;
  const int wid = tid >> 5, l = tid & 31;
  const int wr = wid & 3, wc = wid >> 2;
  const int m0 = mt*64;

  const int arow = (l & 7) + (((l >> 3) & 1) << 3);
  const int achk = l >> 4;
  const int brow = (l & 7) + ((l >> 4) << 3);
  const int bchk = (l >> 3) & 1;
  const int axor = l & 7, bxor = l & 7;

  // prologue: prefetch kt=0 (Z 64 rows x128B h/l + W 64 rows x128B h/l)
  #pragma unroll
  for (int u = 0; u < 2; u++) {
    const int idx = tid + 256*u;
    const int row = idx >> 3, c = idx & 7;
    const uint32_t zgo = (uint32_t)(m0 + row)*1536 + c*16;
    const uint32_t wgo = (uint32_t)row*1536 + c*16;
    const uint32_t so = (uint32_t)row*128 + (uint32_t)((c ^ (row & 7)) << 4);
    cpa16(sb + OG_ZH + so, (const char*)g_Zh + zgo);
    cpa16(sb + OG_ZL + so, (const char*)g_Zl + zgo);
    cpa16(sb + OG_WH + so, (const char*)g_Woth + wgo);
    cpa16(sb + OG_WL + so, (const char*)g_Wotl + wgo);
  }
  asm volatile("cp.async.commit_group;" ::: "memory");

  float acc[4][4] = {};

  for (int kt = 0; kt < 12; kt++) {
    const uint32_t buf = (uint32_t)(kt & 1)*8192;
    const uint32_t sZh = sb + OG_ZH + buf, sZl = sb + OG_ZL + buf;
    const uint32_t sWh = sb + OG_WH + buf, sWl = sb + OG_WL + buf;

    asm volatile("cp.async.wait_group 0;" ::: "memory");
    __syncthreads();

    if (kt < 11) {
      const uint32_t nbuf = (uint32_t)((kt + 1) & 1)*8192;
      #pragma unroll
      for (int u = 0; u < 2; u++) {
        const int idx = tid + 256*u;
        const int row = idx >> 3, c = idx & 7;
        const uint32_t zgo = (uint32_t)(m0 + row)*1536 + (uint32_t)(kt+1)*128 + c*16;
        const uint32_t wgo = (uint32_t)row*1536 + (uint32_t)(kt+1)*128 + c*16;
        const uint32_t so = (uint32_t)row*128 + (uint32_t)((c ^ (row & 7)) << 4);
        cpa16(sb + OG_ZH + nbuf + so, (const char*)g_Zh + zgo);
        cpa16(sb + OG_ZL + nbuf + so, (const char*)g_Zl + zgo);
        cpa16(sb + OG_WH + nbuf + so, (const char*)g_Woth + wgo);
        cpa16(sb + OG_WL + nbuf + so, (const char*)g_Wotl + wgo);
      }
      asm volatile("cp.async.commit_group;" ::: "memory");
    }

    #pragma unroll
    for (int ks = 0; ks < 4; ks++) {
      const int kc = 2*ks;
      uint32_t aH[4], aL[4], bH0[4], bH1[4], bL0[4], bL1[4];
      const uint32_t ac = (uint32_t)(((kc + achk) ^ axor) << 4);
      const uint32_t bc = (uint32_t)(((kc + bchk) ^ bxor) << 4);
      ldmat4(aH, sZh + (uint32_t)(wr*16 + arow)*128 + ac);
      ldmat4(aL, sZl + (uint32_t)(wr*16 + arow)*128 + ac);
      ldmat4(bH0, sWh + (uint32_t)(wc*32      + brow)*128 + bc);
      ldmat4(bH1, sWh + (uint32_t)(wc*32 + 16 + brow)*128 + bc);
      ldmat4(bL0, sWl + (uint32_t)(wc*32      + brow)*128 + bc);
      ldmat4(bL1, sWl + (uint32_t)(wc*32 + 16 + brow)*128 + bc);
      mma16816(acc[0], aH, bH0[0], bH0[1]); mma16816(acc[1], aH, bH0[2], bH0[3]);
      mma16816(acc[2], aH, bH1[0], bH1[1]); mma16816(acc[3], aH, bH1[2], bH1[3]);
      mma16816(acc[0], aH, bL0[0], bL0[1]); mma16816(acc[1], aH, bL0[2], bL0[3]);
      mma16816(acc[2], aH, bL1[0], bL1[1]); mma16816(acc[3], aH, bL1[2], bL1[3]);
      mma16816(acc[0], aL, bH0[0], bH0[1]); mma16816(acc[1], aL, bH0[2], bH0[3]);
      mma16816(acc[2], aL, bH1[0], bH1[1]); mma16816(acc[3], aL, bH1[2], bH1[3]);
    }
  }

  // epilogue: out (8192,64) fp32
  const int r0 = m0 + wr*16 + (l >> 2);
  #pragma unroll
  for (int ni = 0; ni < 4; ni++) {
    const int n = wc*32 + ni*8 + 2*(l & 3);
    *(float2*)(out + (size_t)r0*64 + n)       = make_float2(acc[ni][0], acc[ni][1]);
    *(float2*)(out + (size_t)(r0 + 8)*64 + n) = make_float2(acc[ni][2], acc[ni][3]);
  }
}

// ---------------------------------------------------------------------------
extern "C" void kernel_launch(void* const* d_in, const int* in_sizes, int n_in,
                              void* d_out, int out_size) {
  const float* x  = (const float*)d_in[0];
  const float* Wq = (const float*)d_in[1];
  const float* Wk = (const float*)d_in[2];
  const float* Wv = (const float*)d_in[3];
  const float* Wo = (const float*)d_in[4];
  float* out = (float*)d_out;

  prep_x<<<256, 256>>>(x);
  prep_w<<<dim3(12, 3), 256>>>(Wq, Wk, Wv);
  prep_wo<<<12, 256>>>(Wo);

  cudaFuncSetAttribute(qkv_mma, cudaFuncAttributeMaxDynamicSharedMemorySize,
                       QK_SMEM);
  qkv_mma<<<dim3(12, 64, 3), 256, QK_SMEM>>>();

  cudaFuncSetAttribute(attn_mma, cudaFuncAttributeMaxDynamicSharedMemorySize,
                       SMEM_ATT);
  attn_mma<<<dim3(16, 48), 256, SMEM_ATT>>>();

  cudaFuncSetAttribute(out_mma, cudaFuncAttributeMaxDynamicSharedMemorySize,
                       OG_SMEM);
  out_mma<<<128, 256, OG_SMEM>>>(out);
}

// round 10
// speedup vs baseline: 8.1794x; 1.0852x over previous
#include <cuda_runtime.h>
#include <cuda_fp16.h>
#include <cstdint>

#define TT 2048
#define DD 64
#define NG 48
#define GSZ (TT*DD)        // 131072 elements per flat "head"

// ---- scratch (device globals; no allocation allowed) ----------------------
__device__ __half g_xh[8192*64],  g_xl[8192*64];        // x fp16 hi/lo
__device__ __half g_Wth[3*768*64], g_Wtl[3*768*64];     // W^T [mat][n][k] hi/lo
__device__ __half g_Woth[64*768], g_Wotl[64*768];       // Wo^T [n][k] hi/lo
__device__ __half g_Qh[(size_t)NG*GSZ];
__device__ __half g_Kh[(size_t)NG*GSZ];
__device__ __half g_Vh[(size_t)NG*GSZ];
__device__ __half g_Zh[(size_t)NG*GSZ];
__device__ __half g_Zl[(size_t)NG*GSZ];

// ---- helpers ---------------------------------------------------------------
__device__ __forceinline__ uint32_t smem_u32(const void* p) {
  uint32_t a;
  asm("{ .reg .u64 t; cvta.to.shared.u64 t, %1; cvt.u32.u64 %0, t; }"
      : "=r"(a) : "l"(p));
  return a;
}
__device__ __forceinline__ void ldmat4(uint32_t (&r)[4], uint32_t addr) {
  asm volatile("ldmatrix.sync.aligned.m8n8.x4.shared.b16 {%0,%1,%2,%3}, [%4];"
    : "=r"(r[0]), "=r"(r[1]), "=r"(r[2]), "=r"(r[3]) : "r"(addr));
}
__device__ __forceinline__ void ldmat4t(uint32_t (&r)[4], uint32_t addr) {
  asm volatile("ldmatrix.sync.aligned.m8n8.x4.trans.shared.b16 {%0,%1,%2,%3}, [%4];"
    : "=r"(r[0]), "=r"(r[1]), "=r"(r[2]), "=r"(r[3]) : "r"(addr));
}
__device__ __forceinline__ void mma16816(float (&c)[4], const uint32_t (&a)[4],
                                         uint32_t b0, uint32_t b1) {
  asm volatile("mma.sync.aligned.m16n8k16.row.col.f32.f16.f16.f32 "
    "{%0,%1,%2,%3}, {%4,%5,%6,%7}, {%8,%9}, {%0,%1,%2,%3};"
    : "+f"(c[0]), "+f"(c[1]), "+f"(c[2]), "+f"(c[3])
    : "r"(a[0]), "r"(a[1]), "r"(a[2]), "r"(a[3]), "r"(b0), "r"(b1));
}
__device__ __forceinline__ uint32_t pack_h2(float a, float b) {
  __half2 h = __floats2half2_rn(a, b);
  return *(uint32_t*)&h;
}
__device__ __forceinline__ void cpa16(uint32_t s, const void* g) {
  asm volatile("cp.async.cg.shared.global [%0], [%1], 16;" :: "r"(s), "l"(g));
}

// ---------------------------------------------------------------------------
// prep_x: x fp32 (8192x64) -> g_xh/g_xl fp16.  grid 256, block 256.
// ---------------------------------------------------------------------------
__global__ __launch_bounds__(256) void prep_x(const float* __restrict__ x) {
  const int t = blockIdx.x*256 + threadIdx.x;
  const float4 v0 = *(const float4*)(x + t*8);
  const float4 v1 = *(const float4*)(x + t*8 + 4);
  const float f[8] = {v0.x, v0.y, v0.z, v0.w, v1.x, v1.y, v1.z, v1.w};
  uint32_t h[4], l[4];
  #pragma unroll
  for (int i = 0; i < 4; i++) {
    const float a = f[2*i], b = f[2*i+1];
    const float ha = __half2float(__float2half_rn(a));
    const float hb = __half2float(__float2half_rn(b));
    h[i] = pack_h2(a, b);
    l[i] = pack_h2(a - ha, b - hb);
  }
  *(uint4*)(g_xh + t*8) = make_uint4(h[0], h[1], h[2], h[3]);
  *(uint4*)(g_xl + t*8) = make_uint4(l[0], l[1], l[2], l[3]);
}

// ---------------------------------------------------------------------------
// prep_w: W (64k x 768n) fp32 -> Wt [n][k] fp16 hi/lo.  grid (12, 3), block 256.
// ---------------------------------------------------------------------------
__global__ __launch_bounds__(256) void prep_w(const float* __restrict__ Wq,
                                              const float* __restrict__ Wk,
                                              const float* __restrict__ Wv) {
  __shared__ float s[64*65];
  const int nt = blockIdx.x, mat = blockIdx.y;
  const float* W = (mat == 0) ? Wq : ((mat == 1) ? Wk : Wv);
  const int tid = threadIdx.x;
  const int n0 = nt*64;
  #pragma unroll
  for (int u = 0; u < 4; u++) {
    const int idx = tid + 256*u;
    const int k = idx >> 4, c4 = idx & 15;
    const float4 v = *(const float4*)(W + k*768 + n0 + c4*4);
    s[(c4*4+0)*65 + k] = v.x; s[(c4*4+1)*65 + k] = v.y;
    s[(c4*4+2)*65 + k] = v.z; s[(c4*4+3)*65 + k] = v.w;
  }
  __syncthreads();
  const int n = tid >> 2, k0 = (tid & 3) * 16;
  uint32_t h[8], l[8];
  #pragma unroll
  for (int i = 0; i < 8; i++) {
    const float a = s[n*65 + k0 + 2*i], b = s[n*65 + k0 + 2*i + 1];
    const float ha = __half2float(__float2half_rn(a));
    const float hb = __half2float(__float2half_rn(b));
    h[i] = pack_h2(a, b);
    l[i] = pack_h2(a - ha, b - hb);
  }
  __half* dh = g_Wth + (size_t)(mat*768 + n0 + n)*64 + k0;
  __half* dl = g_Wtl + (size_t)(mat*768 + n0 + n)*64 + k0;
  ((uint4*)dh)[0] = make_uint4(h[0], h[1], h[2], h[3]);
  ((uint4*)dh)[1] = make_uint4(h[4], h[5], h[6], h[7]);
  ((uint4*)dl)[0] = make_uint4(l[0], l[1], l[2], l[3]);
  ((uint4*)dl)[1] = make_uint4(l[4], l[5], l[6], l[7]);
}

// ---------------------------------------------------------------------------
// prep_wo: Wo (768k x 64n) fp32 -> Wot [64][768] fp16 hi/lo.  grid 12, block 256.
// ---------------------------------------------------------------------------
__global__ __launch_bounds__(256) void prep_wo(const float* __restrict__ Wo) {
  __shared__ float s[64*65];
  const int kt = blockIdx.x;
  const int tid = threadIdx.x;
  const int k0g = kt*64;
  #pragma unroll
  for (int u = 0; u < 4; u++) {
    const int idx = tid + 256*u;
    const int k = idx >> 4, c4 = idx & 15;
    const float4 v = *(const float4*)(Wo + (size_t)(k0g + k)*64 + c4*4);
    s[(c4*4+0)*65 + k] = v.x; s[(c4*4+1)*65 + k] = v.y;
    s[(c4*4+2)*65 + k] = v.z; s[(c4*4+3)*65 + k] = v.w;
  }
  __syncthreads();
  const int n = tid >> 2, k0 = (tid & 3) * 16;
  uint32_t h[8], l[8];
  #pragma unroll
  for (int i = 0; i < 8; i++) {
    const float a = s[n*65 + k0 + 2*i], b = s[n*65 + k0 + 2*i + 1];
    const float ha = __half2float(__float2half_rn(a));
    const float hb = __half2float(__float2half_rn(b));
    h[i] = pack_h2(a, b);
    l[i] = pack_h2(a - ha, b - hb);
  }
  __half* dh = g_Woth + (size_t)n*768 + k0g + k0;
  __half* dl = g_Wotl + (size_t)n*768 + k0g + k0;
  ((uint4*)dh)[0] = make_uint4(h[0], h[1], h[2], h[3]);
  ((uint4*)dh)[1] = make_uint4(h[4], h[5], h[6], h[7]);
  ((uint4*)dl)[0] = make_uint4(l[0], l[1], l[2], l[3]);
  ((uint4*)dl)[1] = make_uint4(l[4], l[5], l[6], l[7]);
}

// ---------------------------------------------------------------------------
// qkv_mma: QKV = x @ W via HMMA, 3-term fp16 hi/lo split.  (unchanged)
// grid (12 nt, 64 mt, 3 mat), block 256, tile 128m x 64n.
// ---------------------------------------------------------------------------
#define QK_XH 0
#define QK_XL 16384
#define QK_WH 32768
#define QK_WL 40960
#define QK_SMEM 49152

__global__ __launch_bounds__(256) void qkv_mma() {
  extern __shared__ char smc[];
  const uint32_t sb = smem_u32(smc);
  const uint32_t sXh = sb + QK_XH, sXl = sb + QK_XL;
  const uint32_t sWh = sb + QK_WH, sWl = sb + QK_WL;
  const int nt = blockIdx.x, mt = blockIdx.y, mat = blockIdx.z;
  const int tid = threadIdx.x;
  const int wid = tid >> 5, l = tid & 31;
  const int wr = wid & 3, wc = wid >> 2;
  const int m0 = mt*128, n0 = nt*64;

  const int arow = (l & 7) + (((l >> 3) & 1) << 3);
  const int achk = l >> 4;
  const int brow = (l & 7) + ((l >> 4) << 3);
  const int bchk = (l >> 3) & 1;
  const int axor = l & 7, bxor = l & 7;

  #pragma unroll
  for (int u = 0; u < 4; u++) {
    const int idx = tid + 256*u;
    const int row = idx >> 3, c = idx & 7;
    const uint32_t go = (uint32_t)(m0 + row)*128 + c*16;
    const uint32_t so = (uint32_t)row*128 + (uint32_t)((c ^ (row & 7)) << 4);
    *(uint4*)(smc + QK_XH + so) = *(const uint4*)((const char*)g_xh + go);
    *(uint4*)(smc + QK_XL + so) = *(const uint4*)((const char*)g_xl + go);
  }
  #pragma unroll
  for (int u = 0; u < 2; u++) {
    const int idx = tid + 256*u;
    const int row = idx >> 3, c = idx & 7;
    const uint32_t go = (uint32_t)(mat*768 + n0 + row)*128 + c*16;
    const uint32_t so = (uint32_t)row*128 + (uint32_t)((c ^ (row & 7)) << 4);
    *(uint4*)(smc + QK_WH + so) = *(const uint4*)((const char*)g_Wth + go);
    *(uint4*)(smc + QK_WL + so) = *(const uint4*)((const char*)g_Wtl + go);
  }
  __syncthreads();

  float acc[2][4][4] = {};
  #pragma unroll
  for (int ks = 0; ks < 4; ks++) {
    const int kc = 2*ks;
    uint32_t aH0[4], aH1[4], aL0[4], aL1[4], bH0[4], bH1[4], bL0[4], bL1[4];
    const uint32_t ac = (uint32_t)(((kc + achk) ^ axor) << 4);
    const uint32_t bc = (uint32_t)(((kc + bchk) ^ bxor) << 4);
    ldmat4(aH0, sXh + (uint32_t)(wr*32      + arow)*128 + ac);
    ldmat4(aH1, sXh + (uint32_t)(wr*32 + 16 + arow)*128 + ac);
    ldmat4(aL0, sXl + (uint32_t)(wr*32      + arow)*128 + ac);
    ldmat4(aL1, sXl + (uint32_t)(wr*32 + 16 + arow)*128 + ac);
    ldmat4(bH0, sWh + (uint32_t)(wc*32      + brow)*128 + bc);
    ldmat4(bH1, sWh + (uint32_t)(wc*32 + 16 + brow)*128 + bc);
    ldmat4(bL0, sWl + (uint32_t)(wc*32      + brow)*128 + bc);
    ldmat4(bL1, sWl + (uint32_t)(wc*32 + 16 + brow)*128 + bc);
    mma16816(acc[0][0], aH0, bH0[0], bH0[1]); mma16816(acc[0][1], aH0, bH0[2], bH0[3]);
    mma16816(acc[0][2], aH0, bH1[0], bH1[1]); mma16816(acc[0][3], aH0, bH1[2], bH1[3]);
    mma16816(acc[1][0], aH1, bH0[0], bH0[1]); mma16816(acc[1][1], aH1, bH0[2], bH0[3]);
    mma16816(acc[1][2], aH1, bH1[0], bH1[1]); mma16816(acc[1][3], aH1, bH1[2], bH1[3]);
    mma16816(acc[0][0], aH0, bL0[0], bL0[1]); mma16816(acc[0][1], aH0, bL0[2], bL0[3]);
    mma16816(acc[0][2], aH0, bL1[0], bL1[1]); mma16816(acc[0][3], aH0, bL1[2], bL1[3]);
    mma16816(acc[1][0], aH1, bL0[0], bL0[1]); mma16816(acc[1][1], aH1, bL0[2], bL0[3]);
    mma16816(acc[1][2], aH1, bL1[0], bL1[1]); mma16816(acc[1][3], aH1, bL1[2], bL1[3]);
    mma16816(acc[0][0], aL0, bH0[0], bH0[1]); mma16816(acc[0][1], aL0, bH0[2], bH0[3]);
    mma16816(acc[0][2], aL0, bH1[0], bH1[1]); mma16816(acc[0][3], aL0, bH1[2], bH1[3]);
    mma16816(acc[1][0], aL1, bH0[0], bH0[1]); mma16816(acc[1][1], aL1, bH0[2], bH0[3]);
    mma16816(acc[1][2], aL1, bH1[0], bH1[1]); mma16816(acc[1][3], aL1, bH1[2], bH1[3]);
  }

  #pragma unroll
  for (int mi = 0; mi < 2; mi++) {
    const int r0 = wr*32 + mi*16 + (l >> 2);
    #pragma unroll
    for (int ni = 0; ni < 4; ni++) {
      const int d = wc*32 + ni*8 + 2*(l & 3);
      #pragma unroll
      for (int hh = 0; hh < 2; hh++) {
        const int r = r0 + 8*hh;
        const float a = acc[mi][ni][2*hh+0], bb = acc[mi][ni][2*hh+1];
        const size_t off = (size_t)(m0 + r)*768 + n0 + d;
        if (mat == 0) {
          *(uint32_t*)(g_Qh + off) = pack_h2(a, bb);
        } else if (mat == 1) {
          *(uint32_t*)(g_Kh + off) = pack_h2(a, bb);
        } else {
          *(uint32_t*)(g_Vh + off) = pack_h2(a, bb);
        }
      }
    }
  }
}

// ---------------------------------------------------------------------------
// HMMA flash attention, register-resident P, 4-CTA-per-SM config.
// grid (32 i-tiles, 48 heads), 128 threads = 4 warps; warp w owns i rows
// [w*16, w*16+16) of a 64-row i-tile.  4 independent barrier domains per SM
// decouple softmax/MMA phases.  Z written fp16 hi/lo.
// ---------------------------------------------------------------------------
#define OFF_KH 0         // 8KB (64 rows)
#define OFF_Q  8192      // double buffer, stride 8192
#define OFF_V  24576     // double buffer, stride 8192
#define SMEM_ATT 40960

__global__ __launch_bounds__(128, 4) void attn_mma() {
  extern __shared__ char smc[];
  const uint32_t sb = smem_u32(smc);
  const uint32_t sKh = sb + OFF_KH;

  const int g = blockIdx.y, it = blockIdx.x;
  const int tid = threadIdx.x;
  const int w = tid >> 5, l = tid & 31;

  const char* Qg  = (const char*)(g_Qh + (size_t)g*GSZ);
  const char* Khg = (const char*)(g_Kh + (size_t)g*GSZ);
  const char* Vg  = (const char*)(g_Vh + (size_t)g*GSZ);

  const int arow = (l & 7) + (((l >> 3) & 1) << 3);
  const int achk = l >> 4;
  const int brow = (l & 7) + ((l >> 4) << 3);
  const int bchk = (l >> 3) & 1;
  const int axor = l & 7, bxor = l & 7;

  // K i-tile (plain loads, once): 64 rows -> 512 chunks, 128 threads x4
  #pragma unroll
  for (int u = 0; u < 4; u++) {
    const int idx = tid + 128*u;
    const int row = idx >> 3, c = idx & 7;
    const uint32_t go = (uint32_t)(it*64 + row)*128 + c*16;
    const uint32_t so = (uint32_t)row*128 + (uint32_t)((c ^ (row & 7)) << 4);
    *(uint4*)(smc + OFF_KH + so) = *(const uint4*)(Khg + go);
  }

  // prologue: prefetch jt=0 into buffer 0 (64-row tiles -> 512 chunks each)
  #pragma unroll
  for (int u = 0; u < 4; u++) {
    const int idx = tid + 128*u;
    const int row = idx >> 3, c = idx & 7;
    const uint32_t go = (uint32_t)row*128 + c*16;
    const uint32_t so = (uint32_t)row*128 + (uint32_t)((c ^ (row & 7)) << 4);
    cpa16(sb + OFF_Q + so, Qg + go);
    cpa16(sb + OFF_V + so, Vg + go);
  }
  asm volatile("cp.async.commit_group;" ::: "memory");

  float zacc[8][4] = {};
  float lrow[2] = {0.f, 0.f};

  for (int jt = 0; jt < 32; jt++) {
    const uint32_t qb = sb + OFF_Q + (uint32_t)(jt & 1)*8192;
    const uint32_t vb = sb + OFF_V + (uint32_t)(jt & 1)*8192;

    asm volatile("cp.async.wait_group 0;" ::: "memory");
    __syncthreads();      // buf[cur] visible; all warps done with jt-1

    if (jt < 31) {
      const uint32_t qn = sb + OFF_Q + (uint32_t)((jt + 1) & 1)*8192;
      const uint32_t vn = sb + OFF_V + (uint32_t)((jt + 1) & 1)*8192;
      #pragma unroll
      for (int u = 0; u < 4; u++) {
        const int idx = tid + 128*u;
        const int row = idx >> 3, c = idx & 7;
        const uint32_t go = (uint32_t)((jt + 1)*64 + row)*128 + c*16;
        const uint32_t so = (uint32_t)row*128 + (uint32_t)((c ^ (row & 7)) << 4);
        cpa16(qn + so, Qg + go);
        cpa16(vn + so, Vg + go);
      }
      asm volatile("cp.async.commit_group;" ::: "memory");
    }

    // ---- S = K . Q^T  (m16 per warp, n = 64 j in 8 tiles) ----
    float sacc[8][4] = {};
    #pragma unroll
    for (int ks = 0; ks < 4; ks++) {
      const int kc = 2*ks;
      uint32_t a[4];
      const uint32_t ac = (uint32_t)(((kc + achk) ^ axor) << 4);
      const uint32_t bc = (uint32_t)(((kc + bchk) ^ bxor) << 4);
      ldmat4(a, sKh + (uint32_t)(w*16 + arow)*128 + ac);
      #pragma unroll
      for (int jb = 0; jb < 4; jb++) {
        uint32_t q[4];
        ldmat4(q, qb + (uint32_t)(jb*16 + brow)*128 + bc);
        mma16816(sacc[2*jb],   a, q[0], q[1]);
        mma16816(sacc[2*jb+1], a, q[2], q[3]);
      }
    }

    // ---- softmax (no max) in registers; P packed as A-fragments ----
    uint32_t pa[8], pb[8];
    #pragma unroll
    for (int nt = 0; nt < 8; nt++) {
      const float p0 = __expf(sacc[nt][0] * 0.125f);
      const float p1 = __expf(sacc[nt][1] * 0.125f);
      const float p2 = __expf(sacc[nt][2] * 0.125f);
      const float p3 = __expf(sacc[nt][3] * 0.125f);
      lrow[0] += p0 + p1;
      lrow[1] += p2 + p3;
      pa[nt] = pack_h2(p0, p1);
      pb[nt] = pack_h2(p2, p3);
    }

    // ---- Z += P . V  (k = 64 j in 4 chunks, n = 64 d in 8 tiles) ----
    #pragma unroll
    for (int kj = 0; kj < 4; kj++) {
      const uint32_t A[4] = {pa[2*kj], pb[2*kj], pa[2*kj+1], pb[2*kj+1]};
      #pragma unroll
      for (int d4 = 0; d4 < 4; d4++) {
        uint32_t v[4];
        ldmat4t(v, vb + (uint32_t)(16*kj + arow)*128 +
                   (uint32_t)(((2*d4 + achk) ^ axor) << 4));
        mma16816(zacc[2*d4],   A, v[0], v[1]);
        mma16816(zacc[2*d4+1], A, v[2], v[3]);
      }
    }
  }

  // ---- final row sums (within quad) and epilogue ----
  #pragma unroll
  for (int h = 0; h < 2; h++) {
    float v = lrow[h];
    v += __shfl_xor_sync(0xffffffffu, v, 1);
    v += __shfl_xor_sync(0xffffffffu, v, 2);
    lrow[h] = v;
  }
  const float inv0 = 1.f / lrow[0];
  const float inv1 = 1.f / lrow[1];

  __half* Zh = g_Zh + (size_t)g*GSZ + (size_t)it*64*64;
  __half* Zl = g_Zl + (size_t)g*GSZ + (size_t)it*64*64;
  const int r0 = w*16 + (l >> 2);
  #pragma unroll
  for (int nt = 0; nt < 8; nt++) {
    const int c = nt*8 + 2*(l & 3);
    const float z0 = zacc[nt][0]*inv0, z1 = zacc[nt][1]*inv0;
    const float z2 = zacc[nt][2]*inv1, z3 = zacc[nt][3]*inv1;
    const float h0 = __half2float(__float2half_rn(z0));
    const float h1 = __half2float(__float2half_rn(z1));
    const float h2 = __half2float(__float2half_rn(z2));
    const float h3 = __half2float(__float2half_rn(z3));
    *(uint32_t*)(Zh + (size_t)r0*64 + c)     = pack_h2(z0, z1);
    *(uint32_t*)(Zl + (size_t)r0*64 + c)     = pack_h2(z0 - h0, z1 - h1);
    *(uint32_t*)(Zh + (size_t)(r0+8)*64 + c) = pack_h2(z2, z3);
    *(uint32_t*)(Zl + (size_t)(r0+8)*64 + c) = pack_h2(z2 - h2, z3 - h3);
  }
}

// ---------------------------------------------------------------------------
// out_mma: out = Z @ Wo via HMMA, 3-term split, cp.async double-buffered.
// grid 128 (m-tile 64), block 256 (8 warps 4x2), 12 k-chunks.  (unchanged)
// ---------------------------------------------------------------------------
#define OG_ZH 0          // double buffer, stride 8192
#define OG_ZL 16384      // double buffer, stride 8192
#define OG_WH 32768      // double buffer, stride 8192
#define OG_WL 49152      // double buffer, stride 8192
#define OG_SMEM 65536

__global__ __launch_bounds__(256) void out_mma(float* __restrict__ out) {
  extern __shared__ char smc[];
  const uint32_t sb = smem_u32(smc);
  const int mt = blockIdx.x;
  const int tid = threadIdx.x;
  const int wid = tid >> 5, l = tid & 31;
  const int wr = wid & 3, wc = wid >> 2;
  const int m0 = mt*64;

  const int arow = (l & 7) + (((l >> 3) & 1) << 3);
  const int achk = l >> 4;
  const int brow = (l & 7) + ((l >> 4) << 3);
  const int bchk = (l >> 3) & 1;
  const int axor = l & 7, bxor = l & 7;

  #pragma unroll
  for (int u = 0; u < 2; u++) {
    const int idx = tid + 256*u;
    const int row = idx >> 3, c = idx & 7;
    const uint32_t zgo = (uint32_t)(m0 + row)*1536 + c*16;
    const uint32_t wgo = (uint32_t)row*1536 + c*16;
    const uint32_t so = (uint32_t)row*128 + (uint32_t)((c ^ (row & 7)) << 4);
    cpa16(sb + OG_ZH + so, (const char*)g_Zh + zgo);
    cpa16(sb + OG_ZL + so, (const char*)g_Zl + zgo);
    cpa16(sb + OG_WH + so, (const char*)g_Woth + wgo);
    cpa16(sb + OG_WL + so, (const char*)g_Wotl + wgo);
  }
  asm volatile("cp.async.commit_group;" ::: "memory");

  float acc[4][4] = {};

  for (int kt = 0; kt < 12; kt++) {
    const uint32_t buf = (uint32_t)(kt & 1)*8192;
    const uint32_t sZh = sb + OG_ZH + buf, sZl = sb + OG_ZL + buf;
    const uint32_t sWh = sb + OG_WH + buf, sWl = sb + OG_WL + buf;

    asm volatile("cp.async.wait_group 0;" ::: "memory");
    __syncthreads();

    if (kt < 11) {
      const uint32_t nbuf = (uint32_t)((kt + 1) & 1)*8192;
      #pragma unroll
      for (int u = 0; u < 2; u++) {
        const int idx = tid + 256*u;
        const int row = idx >> 3, c = idx & 7;
        const uint32_t zgo = (uint32_t)(m0 + row)*1536 + (uint32_t)(kt+1)*128 + c*16;
        const uint32_t wgo = (uint32_t)row*1536 + (uint32_t)(kt+1)*128 + c*16;
        const uint32_t so = (uint32_t)row*128 + (uint32_t)((c ^ (row & 7)) << 4);
        cpa16(sb + OG_ZH + nbuf + so, (const char*)g_Zh + zgo);
        cpa16(sb + OG_ZL + nbuf + so, (const char*)g_Zl + zgo);
        cpa16(sb + OG_WH + nbuf + so, (const char*)g_Woth + wgo);
        cpa16(sb + OG_WL + nbuf + so, (const char*)g_Wotl + wgo);
      }
      asm volatile("cp.async.commit_group;" ::: "memory");
    }

    #pragma unroll
    for (int ks = 0; ks < 4; ks++) {
      const int kc = 2*ks;
      uint32_t aH[4], aL[4], bH0[4], bH1[4], bL0[4], bL1[4];
      const uint32_t ac = (uint32_t)(((kc + achk) ^ axor) << 4);
      const uint32_t bc = (uint32_t)(((kc + bchk) ^ bxor) << 4);
      ldmat4(aH, sZh + (uint32_t)(wr*16 + arow)*128 + ac);
      ldmat4(aL, sZl + (uint32_t)(wr*16 + arow)*128 + ac);
      ldmat4(bH0, sWh + (uint32_t)(wc*32      + brow)*128 + bc);
      ldmat4(bH1, sWh + (uint32_t)(wc*32 + 16 + brow)*128 + bc);
      ldmat4(bL0, sWl + (uint32_t)(wc*32      + brow)*128 + bc);
      ldmat4(bL1, sWl + (uint32_t)(wc*32 + 16 + brow)*128 + bc);
      mma16816(acc[0], aH, bH0[0], bH0[1]); mma16816(acc[1], aH, bH0[2], bH0[3]);
      mma16816(acc[2], aH, bH1[0], bH1[1]); mma16816(acc[3], aH, bH1[2], bH1[3]);
      mma16816(acc[0], aH, bL0[0], bL0[1]); mma16816(acc[1], aH, bL0[2], bL0[3]);
      mma16816(acc[2], aH, bL1[0], bL1[1]); mma16816(acc[3], aH, bL1[2], bL1[3]);
      mma16816(acc[0], aL, bH0[0], bH0[1]); mma16816(acc[1], aL, bH0[2], bH0[3]);
      mma16816(acc[2], aL, bH1[0], bH1[1]); mma16816(acc[3], aL, bH1[2], bH1[3]);
    }
  }

  const int r0 = m0 + wr*16 + (l >> 2);
  #pragma unroll
  for (int ni = 0; ni < 4; ni++) {
    const int n = wc*32 + ni*8 + 2*(l & 3);
    *(float2*)(out + (size_t)r0*64 + n)       = make_float2(acc[ni][0], acc[ni][1]);
    *(float2*)(out + (size_t)(r0 + 8)*64 + n) = make_float2(acc[ni][2], acc[ni][3]);
  }
}

// ---------------------------------------------------------------------------
extern "C" void kernel_launch(void* const* d_in, const int* in_sizes, int n_in,
                              void* d_out, int out_size) {
  const float* x  = (const float*)d_in[0];
  const float* Wq = (const float*)d_in[1];
  const float* Wk = (const float*)d_in[2];
  const float* Wv = (const float*)d_in[3];
  const float* Wo = (const float*)d_in[4];
  float* out = (float*)d_out;

  prep_x<<<256, 256>>>(x);
  prep_w<<<dim3(12, 3), 256>>>(Wq, Wk, Wv);
  prep_wo<<<12, 256>>>(Wo);

  cudaFuncSetAttribute(qkv_mma, cudaFuncAttributeMaxDynamicSharedMemorySize,
                       QK_SMEM);
  qkv_mma<<<dim3(12, 64, 3), 256, QK_SMEM>>>();

  cudaFuncSetAttribute(attn_mma, cudaFuncAttributeMaxDynamicSharedMemorySize,
                       SMEM_ATT);
  attn_mma<<<dim3(32, 48), 128, SMEM_ATT>>>();

  cudaFuncSetAttribute(out_mma, cudaFuncAttributeMaxDynamicSharedMemorySize,
                       OG_SMEM);
  out_mma<<<128, 256, OG_SMEM>>>(out);
}

// round 11
// speedup vs baseline: 8.9308x; 1.0919x over previous
#include <cuda_runtime.h>
#include <cuda_fp16.h>
#include <cstdint>

#define TT 2048
#define DD 64
#define NG 48
#define GSZ (TT*DD)        // 131072 elements per flat "head"

// ---- scratch (device globals; no allocation allowed) ----------------------
__device__ __half g_xh[8192*64];                        // x fp16 (hi only)
__device__ __half g_Wth[3*768*64], g_Wtl[3*768*64];     // W^T [mat][n][k] hi/lo
__device__ __half g_Woth[64*768], g_Wotl[64*768];       // Wo^T [n][k] hi/lo
__device__ __half g_Qh[(size_t)NG*GSZ];
__device__ __half g_Kh[(size_t)NG*GSZ];
__device__ __half g_Vh[(size_t)NG*GSZ];
__device__ __half g_Zh[(size_t)NG*GSZ];

// ---- helpers ---------------------------------------------------------------
__device__ __forceinline__ uint32_t smem_u32(const void* p) {
  uint32_t a;
  asm("{ .reg .u64 t; cvta.to.shared.u64 t, %1; cvt.u32.u64 %0, t; }"
      : "=r"(a) : "l"(p));
  return a;
}
__device__ __forceinline__ void ldmat4(uint32_t (&r)[4], uint32_t addr) {
  asm volatile("ldmatrix.sync.aligned.m8n8.x4.shared.b16 {%0,%1,%2,%3}, [%4];"
    : "=r"(r[0]), "=r"(r[1]), "=r"(r[2]), "=r"(r[3]) : "r"(addr));
}
__device__ __forceinline__ void ldmat4t(uint32_t (&r)[4], uint32_t addr) {
  asm volatile("ldmatrix.sync.aligned.m8n8.x4.trans.shared.b16 {%0,%1,%2,%3}, [%4];"
    : "=r"(r[0]), "=r"(r[1]), "=r"(r[2]), "=r"(r[3]) : "r"(addr));
}
__device__ __forceinline__ void mma16816(float (&c)[4], const uint32_t (&a)[4],
                                         uint32_t b0, uint32_t b1) {
  asm volatile("mma.sync.aligned.m16n8k16.row.col.f32.f16.f16.f32 "
    "{%0,%1,%2,%3}, {%4,%5,%6,%7}, {%8,%9}, {%0,%1,%2,%3};"
    : "+f"(c[0]), "+f"(c[1]), "+f"(c[2]), "+f"(c[3])
    : "r"(a[0]), "r"(a[1]), "r"(a[2]), "r"(a[3]), "r"(b0), "r"(b1));
}
__device__ __forceinline__ uint32_t pack_h2(float a, float b) {
  __half2 h = __floats2half2_rn(a, b);
  return *(uint32_t*)&h;
}
__device__ __forceinline__ void cpa16(uint32_t s, const void* g) {
  asm volatile("cp.async.cg.shared.global [%0], [%1], 16;" :: "r"(s), "l"(g));
}

// ---------------------------------------------------------------------------
// prep_all: one launch for all preprocessing.
//   blocks [0,256):   x fp32 -> g_xh fp16 (hi only)
//   blocks [256,292): W{q,k,v} -> Wt [mat][n][k] fp16 hi/lo  (idx = nt + 12*mat)
//   blocks [292,304): Wo -> Wot [64][768] fp16 hi/lo          (kt = idx)
// block 256 threads.
// ---------------------------------------------------------------------------
__global__ __launch_bounds__(256) void prep_all(
    const float* __restrict__ x,  const float* __restrict__ Wq,
    const float* __restrict__ Wk, const float* __restrict__ Wv,
    const float* __restrict__ Wo) {
  __shared__ float s[64*65];
  const int bid = blockIdx.x;
  const int tid = threadIdx.x;

  if (bid < 256) {
    const int t = bid*256 + tid;
    const float4 v0 = *(const float4*)(x + t*8);
    const float4 v1 = *(const float4*)(x + t*8 + 4);
    uint32_t h[4];
    h[0] = pack_h2(v0.x, v0.y); h[1] = pack_h2(v0.z, v0.w);
    h[2] = pack_h2(v1.x, v1.y); h[3] = pack_h2(v1.z, v1.w);
    *(uint4*)(g_xh + t*8) = make_uint4(h[0], h[1], h[2], h[3]);
    return;
  }

  if (bid < 292) {
    const int idx = bid - 256;
    const int nt = idx % 12, mat = idx / 12;
    const float* W = (mat == 0) ? Wq : ((mat == 1) ? Wk : Wv);
    const int n0 = nt*64;
    #pragma unroll
    for (int u = 0; u < 4; u++) {
      const int id2 = tid + 256*u;
      const int k = id2 >> 4, c4 = id2 & 15;
      const float4 v = *(const float4*)(W + k*768 + n0 + c4*4);
      s[(c4*4+0)*65 + k] = v.x; s[(c4*4+1)*65 + k] = v.y;
      s[(c4*4+2)*65 + k] = v.z; s[(c4*4+3)*65 + k] = v.w;
    }
    __syncthreads();
    const int n = tid >> 2, k0 = (tid & 3) * 16;
    uint32_t h[8], l[8];
    #pragma unroll
    for (int i = 0; i < 8; i++) {
      const float a = s[n*65 + k0 + 2*i], b = s[n*65 + k0 + 2*i + 1];
      const float ha = __half2float(__float2half_rn(a));
      const float hb = __half2float(__float2half_rn(b));
      h[i] = pack_h2(a, b);
      l[i] = pack_h2(a - ha, b - hb);
    }
    __half* dh = g_Wth + (size_t)(mat*768 + n0 + n)*64 + k0;
    __half* dl = g_Wtl + (size_t)(mat*768 + n0 + n)*64 + k0;
    ((uint4*)dh)[0] = make_uint4(h[0], h[1], h[2], h[3]);
    ((uint4*)dh)[1] = make_uint4(h[4], h[5], h[6], h[7]);
    ((uint4*)dl)[0] = make_uint4(l[0], l[1], l[2], l[3]);
    ((uint4*)dl)[1] = make_uint4(l[4], l[5], l[6], l[7]);
    return;
  }

  {
    const int kt = bid - 292;
    const int k0g = kt*64;
    #pragma unroll
    for (int u = 0; u < 4; u++) {
      const int id2 = tid + 256*u;
      const int k = id2 >> 4, c4 = id2 & 15;
      const float4 v = *(const float4*)(Wo + (size_t)(k0g + k)*64 + c4*4);
      s[(c4*4+0)*65 + k] = v.x; s[(c4*4+1)*65 + k] = v.y;
      s[(c4*4+2)*65 + k] = v.z; s[(c4*4+3)*65 + k] = v.w;
    }
    __syncthreads();
    const int n = tid >> 2, k0 = (tid & 3) * 16;
    uint32_t h[8], l[8];
    #pragma unroll
    for (int i = 0; i < 8; i++) {
      const float a = s[n*65 + k0 + 2*i], b = s[n*65 + k0 + 2*i + 1];
      const float ha = __half2float(__float2half_rn(a));
      const float hb = __half2float(__float2half_rn(b));
      h[i] = pack_h2(a, b);
      l[i] = pack_h2(a - ha, b - hb);
    }
    __half* dh = g_Woth + (size_t)n*768 + k0g + k0;
    __half* dl = g_Wotl + (size_t)n*768 + k0g + k0;
    ((uint4*)dh)[0] = make_uint4(h[0], h[1], h[2], h[3]);
    ((uint4*)dh)[1] = make_uint4(h[4], h[5], h[6], h[7]);
    ((uint4*)dl)[0] = make_uint4(l[0], l[1], l[2], l[3]);
    ((uint4*)dl)[1] = make_uint4(l[4], l[5], l[6], l[7]);
  }
}

// ---------------------------------------------------------------------------
// qkv_mma: QKV = xh @ (Wh + Wl) via HMMA (2-term split; x lo dropped).
// grid (12 nt, 64 mt, 3 mat), block 256, tile 128m x 64n.
// ---------------------------------------------------------------------------
#define QK_XH 0
#define QK_WH 16384
#define QK_WL 24576
#define QK_SMEM 32768

__global__ __launch_bounds__(256) void qkv_mma() {
  extern __shared__ char smc[];
  const uint32_t sb = smem_u32(smc);
  const uint32_t sXh = sb + QK_XH;
  const uint32_t sWh = sb + QK_WH, sWl = sb + QK_WL;
  const int nt = blockIdx.x, mt = blockIdx.y, mat = blockIdx.z;
  const int tid = threadIdx.x;
  const int wid = tid >> 5, l = tid & 31;
  const int wr = wid & 3, wc = wid >> 2;
  const int m0 = mt*128, n0 = nt*64;

  const int arow = (l & 7) + (((l >> 3) & 1) << 3);
  const int achk = l >> 4;
  const int brow = (l & 7) + ((l >> 4) << 3);
  const int bchk = (l >> 3) & 1;
  const int axor = l & 7, bxor = l & 7;

  #pragma unroll
  for (int u = 0; u < 4; u++) {
    const int idx = tid + 256*u;
    const int row = idx >> 3, c = idx & 7;
    const uint32_t go = (uint32_t)(m0 + row)*128 + c*16;
    const uint32_t so = (uint32_t)row*128 + (uint32_t)((c ^ (row & 7)) << 4);
    *(uint4*)(smc + QK_XH + so) = *(const uint4*)((const char*)g_xh + go);
  }
  #pragma unroll
  for (int u = 0; u < 2; u++) {
    const int idx = tid + 256*u;
    const int row = idx >> 3, c = idx & 7;
    const uint32_t go = (uint32_t)(mat*768 + n0 + row)*128 + c*16;
    const uint32_t so = (uint32_t)row*128 + (uint32_t)((c ^ (row & 7)) << 4);
    *(uint4*)(smc + QK_WH + so) = *(const uint4*)((const char*)g_Wth + go);
    *(uint4*)(smc + QK_WL + so) = *(const uint4*)((const char*)g_Wtl + go);
  }
  __syncthreads();

  float acc[2][4][4] = {};
  #pragma unroll
  for (int ks = 0; ks < 4; ks++) {
    const int kc = 2*ks;
    uint32_t aH0[4], aH1[4], bH0[4], bH1[4], bL0[4], bL1[4];
    const uint32_t ac = (uint32_t)(((kc + achk) ^ axor) << 4);
    const uint32_t bc = (uint32_t)(((kc + bchk) ^ bxor) << 4);
    ldmat4(aH0, sXh + (uint32_t)(wr*32      + arow)*128 + ac);
    ldmat4(aH1, sXh + (uint32_t)(wr*32 + 16 + arow)*128 + ac);
    ldmat4(bH0, sWh + (uint32_t)(wc*32      + brow)*128 + bc);
    ldmat4(bH1, sWh + (uint32_t)(wc*32 + 16 + brow)*128 + bc);
    ldmat4(bL0, sWl + (uint32_t)(wc*32      + brow)*128 + bc);
    ldmat4(bL1, sWl + (uint32_t)(wc*32 + 16 + brow)*128 + bc);
    mma16816(acc[0][0], aH0, bH0[0], bH0[1]); mma16816(acc[0][1], aH0, bH0[2], bH0[3]);
    mma16816(acc[0][2], aH0, bH1[0], bH1[1]); mma16816(acc[0][3], aH0, bH1[2], bH1[3]);
    mma16816(acc[1][0], aH1, bH0[0], bH0[1]); mma16816(acc[1][1], aH1, bH0[2], bH0[3]);
    mma16816(acc[1][2], aH1, bH1[0], bH1[1]); mma16816(acc[1][3], aH1, bH1[2], bH1[3]);
    mma16816(acc[0][0], aH0, bL0[0], bL0[1]); mma16816(acc[0][1], aH0, bL0[2], bL0[3]);
    mma16816(acc[0][2], aH0, bL1[0], bL1[1]); mma16816(acc[0][3], aH0, bL1[2], bL1[3]);
    mma16816(acc[1][0], aH1, bL0[0], bL0[1]); mma16816(acc[1][1], aH1, bL0[2], bL0[3]);
    mma16816(acc[1][2], aH1, bL1[0], bL1[1]); mma16816(acc[1][3], aH1, bL1[2], bL1[3]);
  }

  #pragma unroll
  for (int mi = 0; mi < 2; mi++) {
    const int r0 = wr*32 + mi*16 + (l >> 2);
    #pragma unroll
    for (int ni = 0; ni < 4; ni++) {
      const int d = wc*32 + ni*8 + 2*(l & 3);
      #pragma unroll
      for (int hh = 0; hh < 2; hh++) {
        const int r = r0 + 8*hh;
        const float a = acc[mi][ni][2*hh+0], bb = acc[mi][ni][2*hh+1];
        const size_t off = (size_t)(m0 + r)*768 + n0 + d;
        if (mat == 0) {
          *(uint32_t*)(g_Qh + off) = pack_h2(a, bb);
        } else if (mat == 1) {
          *(uint32_t*)(g_Kh + off) = pack_h2(a, bb);
        } else {
          *(uint32_t*)(g_Vh + off) = pack_h2(a, bb);
        }
      }
    }
  }
}

// ---------------------------------------------------------------------------
// HMMA flash attention, register-resident P, 4-CTA-per-SM config.
// grid (32 i-tiles, 48 heads), 128 threads = 4 warps.  Z written fp16 (hi only).
// ---------------------------------------------------------------------------
#define OFF_KH 0         // 8KB (64 rows)
#define OFF_Q  8192      // double buffer, stride 8192
#define OFF_V  24576     // double buffer, stride 8192
#define SMEM_ATT 40960

__global__ __launch_bounds__(128, 4) void attn_mma() {
  extern __shared__ char smc[];
  const uint32_t sb = smem_u32(smc);
  const uint32_t sKh = sb + OFF_KH;

  const int g = blockIdx.y, it = blockIdx.x;
  const int tid = threadIdx.x;
  const int w = tid >> 5, l = tid & 31;

  const char* Qg  = (const char*)(g_Qh + (size_t)g*GSZ);
  const char* Khg = (const char*)(g_Kh + (size_t)g*GSZ);
  const char* Vg  = (const char*)(g_Vh + (size_t)g*GSZ);

  const int arow = (l & 7) + (((l >> 3) & 1) << 3);
  const int achk = l >> 4;
  const int brow = (l & 7) + ((l >> 4) << 3);
  const int bchk = (l >> 3) & 1;
  const int axor = l & 7, bxor = l & 7;

  // K i-tile (plain loads, once): 64 rows -> 512 chunks, 128 threads x4
  #pragma unroll
  for (int u = 0; u < 4; u++) {
    const int idx = tid + 128*u;
    const int row = idx >> 3, c = idx & 7;
    const uint32_t go = (uint32_t)(it*64 + row)*128 + c*16;
    const uint32_t so = (uint32_t)row*128 + (uint32_t)((c ^ (row & 7)) << 4);
    *(uint4*)(smc + OFF_KH + so) = *(const uint4*)(Khg + go);
  }

  // prologue: prefetch jt=0 into buffer 0
  #pragma unroll
  for (int u = 0; u < 4; u++) {
    const int idx = tid + 128*u;
    const int row = idx >> 3, c = idx & 7;
    const uint32_t go = (uint32_t)row*128 + c*16;
    const uint32_t so = (uint32_t)row*128 + (uint32_t)((c ^ (row & 7)) << 4);
    cpa16(sb + OFF_Q + so, Qg + go);
    cpa16(sb + OFF_V + so, Vg + go);
  }
  asm volatile("cp.async.commit_group;" ::: "memory");

  float zacc[8][4] = {};
  float lrow[2] = {0.f, 0.f};

  for (int jt = 0; jt < 32; jt++) {
    const uint32_t qb = sb + OFF_Q + (uint32_t)(jt & 1)*8192;
    const uint32_t vb = sb + OFF_V + (uint32_t)(jt & 1)*8192;

    asm volatile("cp.async.wait_group 0;" ::: "memory");
    __syncthreads();

    if (jt < 31) {
      const uint32_t qn = sb + OFF_Q + (uint32_t)((jt + 1) & 1)*8192;
      const uint32_t vn = sb + OFF_V + (uint32_t)((jt + 1) & 1)*8192;
      #pragma unroll
      for (int u = 0; u < 4; u++) {
        const int idx = tid + 128*u;
        const int row = idx >> 3, c = idx & 7;
        const uint32_t go = (uint32_t)((jt + 1)*64 + row)*128 + c*16;
        const uint32_t so = (uint32_t)row*128 + (uint32_t)((c ^ (row & 7)) << 4);
        cpa16(qn + so, Qg + go);
        cpa16(vn + so, Vg + go);
      }
      asm volatile("cp.async.commit_group;" ::: "memory");
    }

    // ---- S = K . Q^T ----
    float sacc[8][4] = {};
    #pragma unroll
    for (int ks = 0; ks < 4; ks++) {
      const int kc = 2*ks;
      uint32_t a[4];
      const uint32_t ac = (uint32_t)(((kc + achk) ^ axor) << 4);
      const uint32_t bc = (uint32_t)(((kc + bchk) ^ bxor) << 4);
      ldmat4(a, sKh + (uint32_t)(w*16 + arow)*128 + ac);
      #pragma unroll
      for (int jb = 0; jb < 4; jb++) {
        uint32_t q[4];
        ldmat4(q, qb + (uint32_t)(jb*16 + brow)*128 + bc);
        mma16816(sacc[2*jb],   a, q[0], q[1]);
        mma16816(sacc[2*jb+1], a, q[2], q[3]);
      }
    }

    // ---- softmax (no max) in registers; P packed as A-fragments ----
    uint32_t pa[8], pb[8];
    #pragma unroll
    for (int nt = 0; nt < 8; nt++) {
      const float p0 = __expf(sacc[nt][0] * 0.125f);
      const float p1 = __expf(sacc[nt][1] * 0.125f);
      const float p2 = __expf(sacc[nt][2] * 0.125f);
      const float p3 = __expf(sacc[nt][3] * 0.125f);
      lrow[0] += p0 + p1;
      lrow[1] += p2 + p3;
      pa[nt] = pack_h2(p0, p1);
      pb[nt] = pack_h2(p2, p3);
    }

    // ---- Z += P . V ----
    #pragma unroll
    for (int kj = 0; kj < 4; kj++) {
      const uint32_t A[4] = {pa[2*kj], pb[2*kj], pa[2*kj+1], pb[2*kj+1]};
      #pragma unroll
      for (int d4 = 0; d4 < 4; d4++) {
        uint32_t v[4];
        ldmat4t(v, vb + (uint32_t)(16*kj + arow)*128 +
                   (uint32_t)(((2*d4 + achk) ^ axor) << 4));
        mma16816(zacc[2*d4],   A, v[0], v[1]);
        mma16816(zacc[2*d4+1], A, v[2], v[3]);
      }
    }
  }

  // ---- final row sums and epilogue (Zh only) ----
  #pragma unroll
  for (int h = 0; h < 2; h++) {
    float v = lrow[h];
    v += __shfl_xor_sync(0xffffffffu, v, 1);
    v += __shfl_xor_sync(0xffffffffu, v, 2);
    lrow[h] = v;
  }
  const float inv0 = 1.f / lrow[0];
  const float inv1 = 1.f / lrow[1];

  __half* Zh = g_Zh + (size_t)g*GSZ + (size_t)it*64*64;
  const int r0 = w*16 + (l >> 2);
  #pragma unroll
  for (int nt = 0; nt < 8; nt++) {
    const int c = nt*8 + 2*(l & 3);
    *(uint32_t*)(Zh + (size_t)r0*64 + c) =
        pack_h2(zacc[nt][0]*inv0, zacc[nt][1]*inv0);
    *(uint32_t*)(Zh + (size_t)(r0+8)*64 + c) =
        pack_h2(zacc[nt][2]*inv1, zacc[nt][3]*inv1);
  }
}

// ---------------------------------------------------------------------------
// out_mma: out = Zh @ (Wh + Wl) via HMMA (2-term), cp.async double-buffered.
// grid 128 (m-tile 64), block 256 (8 warps 4x2), 12 k-chunks.
// ---------------------------------------------------------------------------
#define OG_ZH 0          // double buffer, stride 8192
#define OG_WH 16384      // double buffer, stride 8192
#define OG_WL 32768      // double buffer, stride 8192
#define OG_SMEM 49152

__global__ __launch_bounds__(256) void out_mma(float* __restrict__ out) {
  extern __shared__ char smc[];
  const uint32_t sb = smem_u32(smc);
  const int mt = blockIdx.x;
  const int tid = threadIdx.x;
  const int wid = tid >> 5, l = tid & 31;
  const int wr = wid & 3, wc = wid >> 2;
  const int m0 = mt*64;

  const int arow = (l & 7) + (((l >> 3) & 1) << 3);
  const int achk = l >> 4;
  const int brow = (l & 7) + ((l >> 4) << 3);
  const int bchk = (l >> 3) & 1;
  const int axor = l & 7, bxor = l & 7;

  #pragma unroll
  for (int u = 0; u < 2; u++) {
    const int idx = tid + 256*u;
    const int row = idx >> 3, c = idx & 7;
    const uint32_t zgo = (uint32_t)(m0 + row)*1536 + c*16;
    const uint32_t wgo = (uint32_t)row*1536 + c*16;
    const uint32_t so = (uint32_t)row*128 + (uint32_t)((c ^ (row & 7)) << 4);
    cpa16(sb + OG_ZH + so, (const char*)g_Zh + zgo);
    cpa16(sb + OG_WH + so, (const char*)g_Woth + wgo);
    cpa16(sb + OG_WL + so, (const char*)g_Wotl + wgo);
  }
  asm volatile("cp.async.commit_group;" ::: "memory");

  float acc[4][4] = {};

  for (int kt = 0; kt < 12; kt++) {
    const uint32_t buf = (uint32_t)(kt & 1)*8192;
    const uint32_t sZh = sb + OG_ZH + buf;
    const uint32_t sWh = sb + OG_WH + buf, sWl = sb + OG_WL + buf;

    asm volatile("cp.async.wait_group 0;" ::: "memory");
    __syncthreads();

    if (kt < 11) {
      const uint32_t nbuf = (uint32_t)((kt + 1) & 1)*8192;
      #pragma unroll
      for (int u = 0; u < 2; u++) {
        const int idx = tid + 256*u;
        const int row = idx >> 3, c = idx & 7;
        const uint32_t zgo = (uint32_t)(m0 + row)*1536 + (uint32_t)(kt+1)*128 + c*16;
        const uint32_t wgo = (uint32_t)row*1536 + (uint32_t)(kt+1)*128 + c*16;
        const uint32_t so = (uint32_t)row*128 + (uint32_t)((c ^ (row & 7)) << 4);
        cpa16(sb + OG_ZH + nbuf + so, (const char*)g_Zh + zgo);
        cpa16(sb + OG_WH + nbuf + so, (const char*)g_Woth + wgo);
        cpa16(sb + OG_WL + nbuf + so, (const char*)g_Wotl + wgo);
      }
      asm volatile("cp.async.commit_group;" ::: "memory");
    }

    #pragma unroll
    for (int ks = 0; ks < 4; ks++) {
      const int kc = 2*ks;
      uint32_t aH[4], bH0[4], bH1[4], bL0[4], bL1[4];
      const uint32_t ac = (uint32_t)(((kc + achk) ^ axor) << 4);
      const uint32_t bc = (uint32_t)(((kc + bchk) ^ bxor) << 4);
      ldmat4(aH, sZh + (uint32_t)(wr*16 + arow)*128 + ac);
      ldmat4(bH0, sWh + (uint32_t)(wc*32      + brow)*128 + bc);
      ldmat4(bH1, sWh + (uint32_t)(wc*32 + 16 + brow)*128 + bc);
      ldmat4(bL0, sWl + (uint32_t)(wc*32      + brow)*128 + bc);
      ldmat4(bL1, sWl + (uint32_t)(wc*32 + 16 + brow)*128 + bc);
      mma16816(acc[0], aH, bH0[0], bH0[1]); mma16816(acc[1], aH, bH0[2], bH0[3]);
      mma16816(acc[2], aH, bH1[0], bH1[1]); mma16816(acc[3], aH, bH1[2], bH1[3]);
      mma16816(acc[0], aH, bL0[0], bL0[1]); mma16816(acc[1], aH, bL0[2], bL0[3]);
      mma16816(acc[2], aH, bL1[0], bL1[1]); mma16816(acc[3], aH, bL1[2], bL1[3]);
    }
  }

  const int r0 = m0 + wr*16 + (l >> 2);
  #pragma unroll
  for (int ni = 0; ni < 4; ni++) {
    const int n = wc*32 + ni*8 + 2*(l & 3);
    *(float2*)(out + (size_t)r0*64 + n)       = make_float2(acc[ni][0], acc[ni][1]);
    *(float2*)(out + (size_t)(r0 + 8)*64 + n) = make_float2(acc[ni][2], acc[ni][3]);
  }
}

// ---------------------------------------------------------------------------
extern "C" void kernel_launch(void* const* d_in, const int* in_sizes, int n_in,
                              void* d_out, int out_size) {
  const float* x  = (const float*)d_in[0];
  const float* Wq = (const float*)d_in[1];
  const float* Wk = (const float*)d_in[2];
  const float* Wv = (const float*)d_in[3];
  const float* Wo = (const float*)d_in[4];
  float* out = (float*)d_out;

  prep_all<<<304, 256>>>(x, Wq, Wk, Wv, Wo);

  cudaFuncSetAttribute(qkv_mma, cudaFuncAttributeMaxDynamicSharedMemorySize,
                       QK_SMEM);
  qkv_mma<<<dim3(12, 64, 3), 256, QK_SMEM>>>();

  cudaFuncSetAttribute(attn_mma, cudaFuncAttributeMaxDynamicSharedMemorySize,
                       SMEM_ATT);
  attn_mma<<<dim3(32, 48), 128, SMEM_ATT>>>();

  cudaFuncSetAttribute(out_mma, cudaFuncAttributeMaxDynamicSharedMemorySize,
                       OG_SMEM);
  out_mma<<<128, 256, OG_SMEM>>>(out);
}